// round 11
// baseline (speedup 1.0000x reference)
#include <cuda_runtime.h>
#include <cuda_fp16.h>
#include <cstdint>
#include <cstddef>

#define DI 128
#define DO 64
#define NMAX 100000

// B image: [128 n][132 k-pitch] tf32-rounded floats
#define BP 132

// ---------------------------------------------------------------------------
// Scratch
// ---------------------------------------------------------------------------
__device__ __align__(16) float g_scratch[6 * (size_t)NMAX * DO + 6 * (size_t)NMAX];
__device__ __align__(16) float g_B1[128 * BP], g_B2[128 * BP];

__device__ __forceinline__ uint32_t f2tf32(float x) {
    uint32_t r;
    asm("cvt.rna.tf32.f32 %0, %1;" : "=r"(r) : "f"(x));
    return r;
}

__device__ __forceinline__ void mma_tf32(float* c, uint32_t a0, uint32_t a1,
                                         uint32_t a2, uint32_t a3,
                                         uint32_t b0, uint32_t b1) {
    asm volatile("mma.sync.aligned.m16n8k8.row.col.f32.tf32.tf32.f32 "
                 "{%0,%1,%2,%3}, {%4,%5,%6,%7}, {%8,%9}, {%0,%1,%2,%3};"
                 : "+f"(c[0]), "+f"(c[1]), "+f"(c[2]), "+f"(c[3])
                 : "r"(a0), "r"(a1), "r"(a2), "r"(a3), "r"(b0), "r"(b1));
}

// SMEM layout (bytes)
#define OFF_A    0                      // aA[64], aB[64] floats (512B)
#define OFF_B    512                    // 128 x BP floats
#define SMEM_TOT (512 + 128 * BP * 4)   // 68096

// ---------------------------------------------------------------------------
// Arg bundles
// ---------------------------------------------------------------------------
struct GA {
    const float* X;
    const float* B;       // tf32 image
    __half* Yh;           // src-projection (fp16, edge-gather consumer)
    float*  Yf;           // tgt-projection (fp32)
    const float* aA; const float* aB;
    float* sA; float* sB;
    int N;
};
struct EA {
    const int* src; const int* tgt;
    const float* ss; const float* ts;
    const uint2* sxh;
    float4* msg4; float* den;
    int E;
};

// ---------------------------------------------------------------------------
// Prep (merged): B[n][k] = tf32(Wa[k][n]) (n<64) else tf32(Wb[k][n-64]).
// ---------------------------------------------------------------------------
__global__ void pre_w_k(const float* __restrict__ Wa1, const float* __restrict__ Wb1,
                        float* __restrict__ B1,
                        const float* __restrict__ Wa2, const float* __restrict__ Wb2,
                        float* __restrict__ B2) {
    int which = blockIdx.x >> 6;
    int idx = (blockIdx.x & 63) * 256 + threadIdx.x;
    const float* Wa = which ? Wa2 : Wa1;
    const float* Wb = which ? Wb2 : Wb1;
    float* B = which ? B2 : B1;
    int n = idx >> 7, k = idx & 127;
    float w = (n < 64) ? Wa[k * 64 + n] : Wb[k * 64 + (n - 64)];
    uint32_t t = f2tf32(w);
    B[n * BP + k] = __uint_as_float(t);
}

// ---------------------------------------------------------------------------
// zero kernel
// ---------------------------------------------------------------------------
__global__ void zero_k(float* __restrict__ p, size_t nf) {
    size_t i = ((size_t)blockIdx.x * blockDim.x + threadIdx.x) * 4;
    if (i + 4 <= nf) {
        *(float4*)(p + i) = make_float4(0.f, 0.f, 0.f, 0.f);
    } else {
        for (; i < nf; i++) p[i] = 0.f;
    }
}

// ---------------------------------------------------------------------------
// Merged tf32 HMMA GEMM. CTA tile 128x128 (Ya cols 0..63, Yb 64..127).
// Warps: wm(4) x wn(2); warp tile 32 rows x 64 cols = 2 mtiles x 8 ntiles.
// Single-pass tf32 (k8 steps). A direct from gmem (scalar, sector-aligned),
// B from smem (conflict-free, pitch 132). Fused score epilogue.
// wn==0 -> fp16 Yh + score A; wn==1 -> fp32 Yf + score B.
// ---------------------------------------------------------------------------
__global__ __launch_bounds__(256, 2)
void gemm_tc(GA g1, GA g2, int nb1)
{
    extern __shared__ char sm[];
    float* smB = (float*)(sm + OFF_B);
    const int tid = threadIdx.x, wid = tid >> 5, lane = tid & 31;

    const bool first = blockIdx.x < (unsigned)nb1;
    const GA g = first ? g1 : g2;
    const int row0 = (first ? blockIdx.x : blockIdx.x - nb1) * 128;

    // Copy tf32 B image into smem (16896 floats = 4224 float4)
    {
        const float4* bsrc = (const float4*)g.B;
        float4* bdst = (float4*)smB;
        const int n4 = 128 * BP / 4;  // 4224
        for (int i = tid; i < n4; i += 256) bdst[i] = bsrc[i];
    }
    if (tid < 64)       ((float*)(sm + OFF_A))[tid] = __ldg(&g.aA[tid]);
    else if (tid < 128) ((float*)(sm + OFF_A))[tid] = __ldg(&g.aB[tid - 64]);

    const int wm = wid & 3, wn = wid >> 2;
    const int kq = lane & 3;            // k within quad
    const int c0 = kq * 2;              // C-fragment col offset

    const int rb = row0 + wm * 32 + (lane >> 2);
    int rows[4] = {rb, rb + 8, rb + 16, rb + 24};
    bool ok[4];
    const float* xp[4];
#pragma unroll
    for (int m = 0; m < 4; m++) {
        ok[m] = rows[m] < g.N;
        xp[m] = g.X + (size_t)(ok[m] ? rows[m] : 0) * DI + kq;
    }

    __syncthreads();

    // Accumulators: c[mtile*8 + ntile][4]
    float c[16][4];
#pragma unroll
    for (int j = 0; j < 16; j++)
#pragma unroll
        for (int q = 0; q < 4; q++) c[j][q] = 0.f;

    // B lane base: (col)*BP + k ; col = wn*64 + ntile*8 + lane/4
    const int bbase = (wn * 64 + (lane >> 2)) * BP + kq;

#pragma unroll
    for (int s = 0; s < 16; s++) {
        const int ks = s * 8;
        // A fragments (2 mtiles): rows {rb,rb+8} and {rb+16,rb+24}
        float f0  = ok[0] ? xp[0][ks]     : 0.f;
        float f1  = ok[1] ? xp[1][ks]     : 0.f;
        float f2  = ok[2] ? xp[2][ks]     : 0.f;
        float f3  = ok[3] ? xp[3][ks]     : 0.f;
        float f0b = ok[0] ? xp[0][ks + 4] : 0.f;
        float f1b = ok[1] ? xp[1][ks + 4] : 0.f;
        float f2b = ok[2] ? xp[2][ks + 4] : 0.f;
        float f3b = ok[3] ? xp[3][ks + 4] : 0.f;
        uint32_t a00 = f2tf32(f0),  a01 = f2tf32(f1);
        uint32_t a02 = f2tf32(f0b), a03 = f2tf32(f1b);
        uint32_t a10 = f2tf32(f2),  a11 = f2tf32(f3);
        uint32_t a12 = f2tf32(f2b), a13 = f2tf32(f3b);

#pragma unroll
        for (int n = 0; n < 8; n++) {
            int bo = bbase + n * (8 * BP) + ks;
            uint32_t b0 = __float_as_uint(smB[bo]);
            uint32_t b1 = __float_as_uint(smB[bo + 4]);
            mma_tf32(c[n],     a00, a01, a02, a03, b0, b1);
            mma_tf32(c[8 + n], a10, a11, a12, a13, b0, b1);
        }
    }

    // Epilogue: scores from fp32 accumulators; Yh fp16 (wn==0) / Yf fp32 (wn==1)
    const float* av = (const float*)(sm + OFF_A) + wn * 64;
    float* sOut = wn ? g.sB : g.sA;

    float sc[4] = {0.f, 0.f, 0.f, 0.f};
#pragma unroll
    for (int n = 0; n < 8; n++) {
        int col = n * 8 + c0;
        float a0 = av[col], a1 = av[col + 1];
        sc[0] += c[n][0] * a0 + c[n][1] * a1;
        sc[1] += c[n][2] * a0 + c[n][3] * a1;
        sc[2] += c[8 + n][0] * a0 + c[8 + n][1] * a1;
        sc[3] += c[8 + n][2] * a0 + c[8 + n][3] * a1;
        if (wn == 0) {
            if (ok[0]) *(__half2*)&g.Yh[(size_t)rows[0] * DO + col] =
                __floats2half2_rn(c[n][0], c[n][1]);
            if (ok[1]) *(__half2*)&g.Yh[(size_t)rows[1] * DO + col] =
                __floats2half2_rn(c[n][2], c[n][3]);
            if (ok[2]) *(__half2*)&g.Yh[(size_t)rows[2] * DO + col] =
                __floats2half2_rn(c[8 + n][0], c[8 + n][1]);
            if (ok[3]) *(__half2*)&g.Yh[(size_t)rows[3] * DO + col] =
                __floats2half2_rn(c[8 + n][2], c[8 + n][3]);
        } else {
            if (ok[0]) *(float2*)&g.Yf[(size_t)rows[0] * DO + col] = make_float2(c[n][0], c[n][1]);
            if (ok[1]) *(float2*)&g.Yf[(size_t)rows[1] * DO + col] = make_float2(c[n][2], c[n][3]);
            if (ok[2]) *(float2*)&g.Yf[(size_t)rows[2] * DO + col] = make_float2(c[8 + n][0], c[8 + n][1]);
            if (ok[3]) *(float2*)&g.Yf[(size_t)rows[3] * DO + col] = make_float2(c[8 + n][2], c[8 + n][3]);
        }
    }
#pragma unroll
    for (int o = 1; o <= 2; o <<= 1) {
#pragma unroll
        for (int m = 0; m < 4; m++) sc[m] += __shfl_xor_sync(0xffffffffu, sc[m], o);
    }
    if ((lane & 3) == 0) {
#pragma unroll
        for (int m = 0; m < 4; m++)
            if (ok[m]) sOut[rows[m]] = sc[m];
    }
}

// ---------------------------------------------------------------------------
// Merged fused edge scatter (unchanged from R10 best)
// ---------------------------------------------------------------------------
__global__ __launch_bounds__(256, 8) void edge_k(EA e1, EA e2, int nb1)
{
    const bool first = blockIdx.x < (unsigned)nb1;
    const EA a = first ? e1 : e2;
    const int bb = first ? blockIdx.x : blockIdx.x - nb1;

    int g = bb * 16 + (threadIdx.x >> 4);
    int lane = threadIdx.x & 15;
    int e0 = g * 2;
    if (e0 >= a.E) return;
    bool two = (e0 + 1) < a.E;
    int e1i = two ? e0 + 1 : e0;

    int s0 = __ldg(&a.src[e0]);
    int s1 = __ldg(&a.src[e1i]);
    int t0 = __ldg(&a.tgt[e0]);
    int t1 = __ldg(&a.tgt[e1i]);

    float ss0 = __ldg(&a.ss[s0]);
    float ss1 = __ldg(&a.ss[s1]);
    float ts0 = __ldg(&a.ts[t0]);
    float ts1 = __ldg(&a.ts[t1]);
    uint2 u0 = __ldg(&a.sxh[(size_t)s0 * 16 + lane]);
    uint2 u1 = __ldg(&a.sxh[(size_t)s1 * 16 + lane]);

    float sc0 = ss0 + ts0;
    float sc1 = ss1 + ts1;
    float at0 = expf(sc0 >= 0.f ? sc0 : 0.2f * sc0);
    float at1 = expf(sc1 >= 0.f ? sc1 : 0.2f * sc1);

    float2 f00 = __half22float2(*(__half2*)&u0.x);
    float2 f01 = __half22float2(*(__half2*)&u0.y);
    float2 f10 = __half22float2(*(__half2*)&u1.x);
    float2 f11 = __half22float2(*(__half2*)&u1.y);

    float4* p0 = &a.msg4[(size_t)t0 * 16 + lane];
    asm volatile("red.global.add.v4.f32 [%0], {%1,%2,%3,%4};"
                 :: "l"(p0), "f"(f00.x * at0), "f"(f00.y * at0),
                    "f"(f01.x * at0), "f"(f01.y * at0) : "memory");
    if (two) {
        float4* p1 = &a.msg4[(size_t)t1 * 16 + lane];
        asm volatile("red.global.add.v4.f32 [%0], {%1,%2,%3,%4};"
                     :: "l"(p1), "f"(f10.x * at1), "f"(f10.y * at1),
                        "f"(f11.x * at1), "f"(f11.y * at1) : "memory");
    }
    if (lane == 0) {
        atomicAdd(&a.den[t0], at0);
        if (two) atomicAdd(&a.den[t1], at1);
    }
}

// ---------------------------------------------------------------------------
// Merged finalize: out = tx + msg / (den + eps)
// ---------------------------------------------------------------------------
__global__ __launch_bounds__(256) void final_k(
    const float4* __restrict__ txu, const float4* __restrict__ msgu,
    const float* __restrict__ denu,
    const float4* __restrict__ txi, const float4* __restrict__ msgi,
    const float* __restrict__ deni,
    float4* __restrict__ out, int n4u, int n4tot)
{
    int i = blockIdx.x * blockDim.x + threadIdx.x;
    if (i >= n4tot) return;
    const float4* txp; const float4* msg; const float* den;
    int li;
    if (i < n4u) { txp = txu; msg = msgu; den = denu; li = i; }
    else         { txp = txi; msg = msgi; den = deni; li = i - n4u; }
    int node = li >> 4;
    float inv = 1.f / (den[node] + 1e-6f);
    float4 m = msg[li];
    float4 t = txp[li];
    out[i] = make_float4(t.x + m.x * inv, t.y + m.y * inv,
                         t.z + m.z * inv, t.w + m.w * inv);
}

// ---------------------------------------------------------------------------
extern "C" void kernel_launch(void* const* d_in, const int* in_sizes, int n_in,
                              void* d_out, int out_size)
{
    const float* x_user   = (const float*)d_in[0];
    const float* x_item   = (const float*)d_in[1];
    const float* W_ui_src = (const float*)d_in[2];
    const float* W_ui_tgt = (const float*)d_in[3];
    const float* W_iu_src = (const float*)d_in[4];
    const float* W_iu_tgt = (const float*)d_in[5];
    const float* a_ui     = (const float*)d_in[6];
    const float* a_iu     = (const float*)d_in[7];
    const int*   edge_ui  = (const int*)d_in[8];
    const int*   edge_iu  = (const int*)d_in[9];
    float* out = (float*)d_out;

    const int Nu  = in_sizes[0] / DI;
    const int Ni  = in_sizes[1] / DI;
    const int Eui = in_sizes[8] / 2;
    const int Eiu = in_sizes[9] / 2;

    float* base = nullptr;
    cudaGetSymbolAddress((void**)&base, g_scratch);
    float *B1, *B2;
    cudaGetSymbolAddress((void**)&B1, g_B1);
    cudaGetSymbolAddress((void**)&B2, g_B2);

    float* s = base;
    __half* sxh_ui = (__half*)s; s += (size_t)Nu * DO / 2;
    float*  tx_iu  = s;          s += (size_t)Nu * DO;
    __half* sxh_iu = (__half*)s; s += (size_t)Ni * DO / 2;
    float*  tx_ui  = s;          s += (size_t)Ni * DO;
    float*  msg_ui = s;          s += (size_t)Ni * DO;
    float*  msg_iu = s;          s += (size_t)Nu * DO;
    float*  den_ui = s;          s += Ni;
    float*  den_iu = s;          s += Nu;
    float*  ss_ui  = s;          s += Nu;
    float*  ts_ui  = s;          s += Ni;
    float*  ss_iu  = s;          s += Ni;
    float*  ts_iu  = s;          s += Nu;

    cudaFuncSetAttribute(gemm_tc, cudaFuncAttributeMaxDynamicSharedMemorySize, SMEM_TOT);

    // Zero msg + den (contiguous from msg_ui)
    {
        size_t zf = (size_t)(Ni + Nu) * DO + (size_t)Ni + (size_t)Nu;
        int blocks = (int)((zf / 4 + 255) / 256) + 1;
        zero_k<<<blocks, 256>>>(msg_ui, zf);
    }

    // Prep tf32 B images (merged)
    pre_w_k<<<128, 256>>>(W_ui_src, W_iu_tgt, B1,
                          W_iu_src, W_ui_tgt, B2);

    // Merged tf32 projections + fused node scores
    {
        GA g1 = {x_user, B1, sxh_ui, tx_iu, a_ui, a_iu + DO, ss_ui, ts_iu, Nu};
        GA g2 = {x_item, B2, sxh_iu, tx_ui, a_iu, a_ui + DO, ss_iu, ts_ui, Ni};
        int nb1 = (Nu + 127) / 128;
        int nb2 = (Ni + 127) / 128;
        gemm_tc<<<nb1 + nb2, 256, SMEM_TOT>>>(g1, g2, nb1);
    }

    // Merged fused edge scatter (fp16 gather)
    {
        EA e1 = {edge_ui, edge_ui + Eui, ss_ui, ts_ui,
                 (const uint2*)sxh_ui, (float4*)msg_ui, den_ui, Eui};
        EA e2 = {edge_iu, edge_iu + Eiu, ss_iu, ts_iu,
                 (const uint2*)sxh_iu, (float4*)msg_iu, den_iu, Eiu};
        int nb1 = (Eui + 31) / 32;
        int nb2 = (Eiu + 31) / 32;
        edge_k<<<nb1 + nb2, 256>>>(e1, e2, nb1);
    }

    // Merged finalize
    {
        int n4u = Nu * 16, n4tot = (Nu + Ni) * 16;
        final_k<<<(n4tot + 255) / 256, 256>>>(
            (const float4*)tx_iu, (const float4*)msg_iu, den_iu,
            (const float4*)tx_ui, (const float4*)msg_ui, den_ui,
            (float4*)out, n4u, n4tot);
    }
}

// round 12
// speedup vs baseline: 1.1491x; 1.1491x over previous
#include <cuda_runtime.h>
#include <cuda_fp16.h>
#include <cstdint>
#include <cstddef>

#define DI 128
#define DO 64
#define NMAX 100000

// B image layout: [128 n][136 k-pitch] fp16 (272B row pitch)
#define BPITCH 136

// ---------------------------------------------------------------------------
// Scratch
// ---------------------------------------------------------------------------
__device__ __align__(16) float g_scratch[6 * (size_t)NMAX * DO + 6 * (size_t)NMAX];
__device__ __align__(16) __half g_B1[128 * BPITCH], g_B2[128 * BPITCH];

__device__ __forceinline__ uint32_t smem_u32(const void* p) {
    uint32_t a;
    asm("{ .reg .u64 t; cvta.to.shared.u64 t, %1; cvt.u32.u64 %0, t; }"
        : "=r"(a) : "l"(p));
    return a;
}

__device__ __forceinline__ void ldm_x4(uint32_t* r, uint32_t addr) {
    asm volatile("ldmatrix.sync.aligned.m8n8.x4.shared.b16 {%0,%1,%2,%3}, [%4];"
                 : "=r"(r[0]), "=r"(r[1]), "=r"(r[2]), "=r"(r[3]) : "r"(addr));
}

__device__ __forceinline__ void mma_f16(float* c, const uint32_t* a,
                                        uint32_t b0, uint32_t b1) {
    asm volatile("mma.sync.aligned.m16n8k16.row.col.f32.f16.f16.f32 "
                 "{%0,%1,%2,%3}, {%4,%5,%6,%7}, {%8,%9}, {%0,%1,%2,%3};"
                 : "+f"(c[0]), "+f"(c[1]), "+f"(c[2]), "+f"(c[3])
                 : "r"(a[0]), "r"(a[1]), "r"(a[2]), "r"(a[3]),
                   "r"(b0), "r"(b1));
}

// SMEM layout (bytes). B tile: 128 rows x 272B pitch
#define XPITCH 272
#define OFF_A    0                       // aA[64], aB[64] floats (512B)
#define OFF_B    512
#define SMEM_TOT (OFF_B + 128 * XPITCH)  // 35328

// ---------------------------------------------------------------------------
// Arg bundles for merged launches
// ---------------------------------------------------------------------------
struct GA {
    const float* X;
    const __half* B;      // fp16 B image
    __half* Yh;           // src-projection (fp16, edge-gather consumer)
    float*  Yf;           // tgt-projection (fp32)
    const float* aA; const float* aB;
    float* sA; float* sB;
    int N;
};
struct EA {
    const int* src; const int* tgt;
    const float* ss; const float* ts;
    const uint2* sxh;
    float4* msg4; float* den;
    int E;
};

// ---------------------------------------------------------------------------
// Prep (merged): B[n][k] = fp16(Wa[k][n]) (n<64) else fp16(Wb[k][n-64]).
// ---------------------------------------------------------------------------
__global__ void pre_w_k(const float* __restrict__ Wa1, const float* __restrict__ Wb1,
                        __half* __restrict__ B1,
                        const float* __restrict__ Wa2, const float* __restrict__ Wb2,
                        __half* __restrict__ B2) {
    int which = blockIdx.x >> 6;
    int idx = (blockIdx.x & 63) * 256 + threadIdx.x;
    const float* Wa = which ? Wa2 : Wa1;
    const float* Wb = which ? Wb2 : Wb1;
    __half* B = which ? B2 : B1;
    int n = idx >> 7, k = idx & 127;
    float w = (n < 64) ? Wa[k * 64 + n] : Wb[k * 64 + (n - 64)];
    B[n * BPITCH + k] = __float2half_rn(w);
}

// ---------------------------------------------------------------------------
// zero kernel
// ---------------------------------------------------------------------------
__global__ void zero_k(float* __restrict__ p, size_t nf) {
    size_t i = ((size_t)blockIdx.x * blockDim.x + threadIdx.x) * 4;
    if (i + 4 <= nf) {
        *(float4*)(p + i) = make_float4(0.f, 0.f, 0.f, 0.f);
    } else {
        for (; i < nf; i++) p[i] = 0.f;
    }
}

// ---------------------------------------------------------------------------
// Merged fp16 HMMA GEMM, warp tiling 4M x 2N (R6 structure, single pass).
// CTA tile 128 rows x 128 cols (Ya cols 0..63, Yb 64..127), K=128.
// A fragments from gmem (float2, cvt to half2 in regs); B via ldmatrix.
// wn==0 -> fp16 Yh + score A; wn==1 -> fp32 Yf + score B.
// Scores from fp32 accumulators.
// ---------------------------------------------------------------------------
__global__ __launch_bounds__(256, 2)
void gemm_tc(GA g1, GA g2, int nb1)
{
    extern __shared__ char sm[];
    const uint32_t sb = smem_u32(sm);
    const int tid = threadIdx.x, wid = tid >> 5, lane = tid & 31;

    const bool first = blockIdx.x < (unsigned)nb1;
    const GA g = first ? g1 : g2;
    const int row0 = (first ? blockIdx.x : blockIdx.x - nb1) * 128;

    // Copy fp16 B image into smem ([128][BPITCH] halves = 2176 float4)
    {
        const float4* bsrc = (const float4*)g.B;
        float4* bdst = (float4*)(sm + OFF_B);
        const int n4 = 128 * BPITCH * 2 / 16;   // 2176
        for (int i = tid; i < n4; i += 256) bdst[i] = bsrc[i];
    }
    if (tid < 64)       ((float*)(sm + OFF_A))[tid] = __ldg(&g.aA[tid]);
    else if (tid < 128) ((float*)(sm + OFF_A))[tid] = __ldg(&g.aB[tid - 64]);

    const int wm = wid & 3, wn = wid >> 2;
    const int c0 = (lane & 3) * 2;

    const int rb = row0 + wm * 32 + (lane >> 2);
    int rows[4] = {rb, rb + 8, rb + 16, rb + 24};
    bool ok[4];
    const float* xp[4];
#pragma unroll
    for (int m = 0; m < 4; m++) {
        ok[m] = rows[m] < g.N;
        xp[m] = g.X + (size_t)(ok[m] ? rows[m] : 0) * DI + c0;
    }

    __syncthreads();

    float c[16][4];
#pragma unroll
    for (int j = 0; j < 16; j++)
#pragma unroll
        for (int q = 0; q < 4; q++) c[j][q] = 0.f;

    const int brow = (lane & 7) + ((lane >> 4) & 1) * 8;
    const int bkk  = ((lane >> 3) & 1) * 8;
    const uint32_t bbase = sb + OFF_B + (wn * 64 + brow) * XPITCH + bkk * 2;

#pragma unroll
    for (int s = 0; s < 8; s++) {
        const int ks = s * 16;
        float2 v[8];
#pragma unroll
        for (int m = 0; m < 4; m++) {
            v[m]     = ok[m] ? *(const float2*)(xp[m] + ks)     : make_float2(0.f, 0.f);
            v[m + 4] = ok[m] ? *(const float2*)(xp[m] + ks + 8) : make_float2(0.f, 0.f);
        }
        uint32_t ah0[4], ah1[4];
        {
            __half2 h;
            h = __floats2half2_rn(v[0].x, v[0].y); ah0[0] = *(uint32_t*)&h;
            h = __floats2half2_rn(v[1].x, v[1].y); ah0[1] = *(uint32_t*)&h;
            h = __floats2half2_rn(v[4].x, v[4].y); ah0[2] = *(uint32_t*)&h;
            h = __floats2half2_rn(v[5].x, v[5].y); ah0[3] = *(uint32_t*)&h;
            h = __floats2half2_rn(v[2].x, v[2].y); ah1[0] = *(uint32_t*)&h;
            h = __floats2half2_rn(v[3].x, v[3].y); ah1[1] = *(uint32_t*)&h;
            h = __floats2half2_rn(v[6].x, v[6].y); ah1[2] = *(uint32_t*)&h;
            h = __floats2half2_rn(v[7].x, v[7].y); ah1[3] = *(uint32_t*)&h;
        }

#pragma unroll
        for (int p = 0; p < 4; p++) {
            uint32_t bh[4];
            uint32_t boff = (uint32_t)(p * 16) * XPITCH + ks * 2;
            ldm_x4(bh, bbase + boff);
            mma_f16(c[2 * p],         ah0, bh[0], bh[1]);
            mma_f16(c[2 * p + 1],     ah0, bh[2], bh[3]);
            mma_f16(c[8 + 2 * p],     ah1, bh[0], bh[1]);
            mma_f16(c[8 + 2 * p + 1], ah1, bh[2], bh[3]);
        }
    }

    const float* av = (const float*)(sm + OFF_A) + wn * 64;
    float* sOut = wn ? g.sB : g.sA;

    float sc[4] = {0.f, 0.f, 0.f, 0.f};
#pragma unroll
    for (int n = 0; n < 8; n++) {
        int col = n * 8 + c0;
        float a0 = av[col], a1 = av[col + 1];
        sc[0] += c[n][0] * a0 + c[n][1] * a1;
        sc[1] += c[n][2] * a0 + c[n][3] * a1;
        sc[2] += c[8 + n][0] * a0 + c[8 + n][1] * a1;
        sc[3] += c[8 + n][2] * a0 + c[8 + n][3] * a1;
        if (wn == 0) {
            if (ok[0]) *(__half2*)&g.Yh[(size_t)rows[0] * DO + col] =
                __floats2half2_rn(c[n][0], c[n][1]);
            if (ok[1]) *(__half2*)&g.Yh[(size_t)rows[1] * DO + col] =
                __floats2half2_rn(c[n][2], c[n][3]);
            if (ok[2]) *(__half2*)&g.Yh[(size_t)rows[2] * DO + col] =
                __floats2half2_rn(c[8 + n][0], c[8 + n][1]);
            if (ok[3]) *(__half2*)&g.Yh[(size_t)rows[3] * DO + col] =
                __floats2half2_rn(c[8 + n][2], c[8 + n][3]);
        } else {
            if (ok[0]) *(float2*)&g.Yf[(size_t)rows[0] * DO + col] = make_float2(c[n][0], c[n][1]);
            if (ok[1]) *(float2*)&g.Yf[(size_t)rows[1] * DO + col] = make_float2(c[n][2], c[n][3]);
            if (ok[2]) *(float2*)&g.Yf[(size_t)rows[2] * DO + col] = make_float2(c[8 + n][0], c[8 + n][1]);
            if (ok[3]) *(float2*)&g.Yf[(size_t)rows[3] * DO + col] = make_float2(c[8 + n][2], c[8 + n][3]);
        }
    }
#pragma unroll
    for (int o = 1; o <= 2; o <<= 1) {
#pragma unroll
        for (int m = 0; m < 4; m++) sc[m] += __shfl_xor_sync(0xffffffffu, sc[m], o);
    }
    if ((lane & 3) == 0) {
#pragma unroll
        for (int m = 0; m < 4; m++)
            if (ok[m]) sOut[rows[m]] = sc[m];
    }
}

// ---------------------------------------------------------------------------
// Merged fused edge scatter (R10 best): 16 lanes per edge, 2 edges/group,
// fp16 feature gather, fp32 red.v4 message accumulation.
// ---------------------------------------------------------------------------
__global__ __launch_bounds__(256, 8) void edge_k(EA e1, EA e2, int nb1)
{
    const bool first = blockIdx.x < (unsigned)nb1;
    const EA a = first ? e1 : e2;
    const int bb = first ? blockIdx.x : blockIdx.x - nb1;

    int g = bb * 16 + (threadIdx.x >> 4);
    int lane = threadIdx.x & 15;
    int e0 = g * 2;
    if (e0 >= a.E) return;
    bool two = (e0 + 1) < a.E;
    int e1i = two ? e0 + 1 : e0;

    int s0 = __ldg(&a.src[e0]);
    int s1 = __ldg(&a.src[e1i]);
    int t0 = __ldg(&a.tgt[e0]);
    int t1 = __ldg(&a.tgt[e1i]);

    float ss0 = __ldg(&a.ss[s0]);
    float ss1 = __ldg(&a.ss[s1]);
    float ts0 = __ldg(&a.ts[t0]);
    float ts1 = __ldg(&a.ts[t1]);
    uint2 u0 = __ldg(&a.sxh[(size_t)s0 * 16 + lane]);
    uint2 u1 = __ldg(&a.sxh[(size_t)s1 * 16 + lane]);

    float sc0 = ss0 + ts0;
    float sc1 = ss1 + ts1;
    float at0 = expf(sc0 >= 0.f ? sc0 : 0.2f * sc0);
    float at1 = expf(sc1 >= 0.f ? sc1 : 0.2f * sc1);

    float2 f00 = __half22float2(*(__half2*)&u0.x);
    float2 f01 = __half22float2(*(__half2*)&u0.y);
    float2 f10 = __half22float2(*(__half2*)&u1.x);
    float2 f11 = __half22float2(*(__half2*)&u1.y);

    float4* p0 = &a.msg4[(size_t)t0 * 16 + lane];
    asm volatile("red.global.add.v4.f32 [%0], {%1,%2,%3,%4};"
                 :: "l"(p0), "f"(f00.x * at0), "f"(f00.y * at0),
                    "f"(f01.x * at0), "f"(f01.y * at0) : "memory");
    if (two) {
        float4* p1 = &a.msg4[(size_t)t1 * 16 + lane];
        asm volatile("red.global.add.v4.f32 [%0], {%1,%2,%3,%4};"
                     :: "l"(p1), "f"(f10.x * at1), "f"(f10.y * at1),
                        "f"(f11.x * at1), "f"(f11.y * at1) : "memory");
    }
    if (lane == 0) {
        atomicAdd(&a.den[t0], at0);
        if (two) atomicAdd(&a.den[t1], at1);
    }
}

// ---------------------------------------------------------------------------
// Merged finalize: out = tx + msg / (den + eps)
// ---------------------------------------------------------------------------
__global__ __launch_bounds__(256) void final_k(
    const float4* __restrict__ txu, const float4* __restrict__ msgu,
    const float* __restrict__ denu,
    const float4* __restrict__ txi, const float4* __restrict__ msgi,
    const float* __restrict__ deni,
    float4* __restrict__ out, int n4u, int n4tot)
{
    int i = blockIdx.x * blockDim.x + threadIdx.x;
    if (i >= n4tot) return;
    const float4* txp; const float4* msg; const float* den;
    int li;
    if (i < n4u) { txp = txu; msg = msgu; den = denu; li = i; }
    else         { txp = txi; msg = msgi; den = deni; li = i - n4u; }
    int node = li >> 4;
    float inv = 1.f / (den[node] + 1e-6f);
    float4 m = msg[li];
    float4 t = txp[li];
    out[i] = make_float4(t.x + m.x * inv, t.y + m.y * inv,
                         t.z + m.z * inv, t.w + m.w * inv);
}

// ---------------------------------------------------------------------------
extern "C" void kernel_launch(void* const* d_in, const int* in_sizes, int n_in,
                              void* d_out, int out_size)
{
    const float* x_user   = (const float*)d_in[0];
    const float* x_item   = (const float*)d_in[1];
    const float* W_ui_src = (const float*)d_in[2];
    const float* W_ui_tgt = (const float*)d_in[3];
    const float* W_iu_src = (const float*)d_in[4];
    const float* W_iu_tgt = (const float*)d_in[5];
    const float* a_ui     = (const float*)d_in[6];
    const float* a_iu     = (const float*)d_in[7];
    const int*   edge_ui  = (const int*)d_in[8];
    const int*   edge_iu  = (const int*)d_in[9];
    float* out = (float*)d_out;

    const int Nu  = in_sizes[0] / DI;
    const int Ni  = in_sizes[1] / DI;
    const int Eui = in_sizes[8] / 2;
    const int Eiu = in_sizes[9] / 2;

    float* base = nullptr;
    cudaGetSymbolAddress((void**)&base, g_scratch);
    __half *B1, *B2;
    cudaGetSymbolAddress((void**)&B1, g_B1);
    cudaGetSymbolAddress((void**)&B2, g_B2);

    float* s = base;
    __half* sxh_ui = (__half*)s; s += (size_t)Nu * DO / 2;
    float*  tx_iu  = s;          s += (size_t)Nu * DO;
    __half* sxh_iu = (__half*)s; s += (size_t)Ni * DO / 2;
    float*  tx_ui  = s;          s += (size_t)Ni * DO;
    float*  msg_ui = s;          s += (size_t)Ni * DO;
    float*  msg_iu = s;          s += (size_t)Nu * DO;
    float*  den_ui = s;          s += Ni;
    float*  den_iu = s;          s += Nu;
    float*  ss_ui  = s;          s += Nu;
    float*  ts_ui  = s;          s += Ni;
    float*  ss_iu  = s;          s += Ni;
    float*  ts_iu  = s;          s += Nu;

    cudaFuncSetAttribute(gemm_tc, cudaFuncAttributeMaxDynamicSharedMemorySize, SMEM_TOT);

    // Zero msg + den (contiguous from msg_ui)
    {
        size_t zf = (size_t)(Ni + Nu) * DO + (size_t)Ni + (size_t)Nu;
        int blocks = (int)((zf / 4 + 255) / 256) + 1;
        zero_k<<<blocks, 256>>>(msg_ui, zf);
    }

    // Prep fp16 B images (merged)
    pre_w_k<<<128, 256>>>(W_ui_src, W_iu_tgt, B1,
                          W_iu_src, W_ui_tgt, B2);

    // Merged fp16 projections + fused node scores
    {
        GA g1 = {x_user, B1, sxh_ui, tx_iu, a_ui, a_iu + DO, ss_ui, ts_iu, Nu};
        GA g2 = {x_item, B2, sxh_iu, tx_ui, a_iu, a_ui + DO, ss_iu, ts_ui, Ni};
        int nb1 = (Nu + 127) / 128;
        int nb2 = (Ni + 127) / 128;
        gemm_tc<<<nb1 + nb2, 256, SMEM_TOT>>>(g1, g2, nb1);
    }

    // Merged fused edge scatter (fp16 gather)
    {
        EA e1 = {edge_ui, edge_ui + Eui, ss_ui, ts_ui,
                 (const uint2*)sxh_ui, (float4*)msg_ui, den_ui, Eui};
        EA e2 = {edge_iu, edge_iu + Eiu, ss_iu, ts_iu,
                 (const uint2*)sxh_iu, (float4*)msg_iu, den_iu, Eiu};
        int nb1 = (Eui + 31) / 32;
        int nb2 = (Eiu + 31) / 32;
        edge_k<<<nb1 + nb2, 256>>>(e1, e2, nb1);
    }

    // Merged finalize
    {
        int n4u = Nu * 16, n4tot = (Nu + Ni) * 16;
        final_k<<<(n4tot + 255) / 256, 256>>>(
            (const float4*)tx_iu, (const float4*)msg_iu, den_iu,
            (const float4*)tx_ui, (const float4*)msg_ui, den_ui,
            (float4*)out, n4u, n4tot);
    }
}

// round 14
// speedup vs baseline: 1.2782x; 1.1123x over previous
#include <cuda_runtime.h>
#include <cuda_fp16.h>
#include <cstdint>
#include <cstddef>

#define DI 128
#define DO 64
#define NMAX 100000
#define EMAX 1048576

// B image layout: [128 n][136 k-pitch] fp16 (272B row pitch)
#define BPITCH 136

// ---------------------------------------------------------------------------
// Scratch
// ---------------------------------------------------------------------------
__device__ __align__(16) float g_scratch[6 * (size_t)NMAX * DO + 6 * (size_t)NMAX];
__device__ __align__(16) __half g_B1[128 * BPITCH], g_B2[128 * BPITCH];

__device__ __forceinline__ uint32_t smem_u32(const void* p) {
    uint32_t a;
    asm("{ .reg .u64 t; cvta.to.shared.u64 t, %1; cvt.u32.u64 %0, t; }"
        : "=r"(a) : "l"(p));
    return a;
}

__device__ __forceinline__ void ldm_x4(uint32_t* r, uint32_t addr) {
    asm volatile("ldmatrix.sync.aligned.m8n8.x4.shared.b16 {%0,%1,%2,%3}, [%4];"
                 : "=r"(r[0]), "=r"(r[1]), "=r"(r[2]), "=r"(r[3]) : "r"(addr));
}

__device__ __forceinline__ void mma_f16(float* c, const uint32_t* a,
                                        uint32_t b0, uint32_t b1) {
    asm volatile("mma.sync.aligned.m16n8k16.row.col.f32.f16.f16.f32 "
                 "{%0,%1,%2,%3}, {%4,%5,%6,%7}, {%8,%9}, {%0,%1,%2,%3};"
                 : "+f"(c[0]), "+f"(c[1]), "+f"(c[2]), "+f"(c[3])
                 : "r"(a[0]), "r"(a[1]), "r"(a[2]), "r"(a[3]),
                   "r"(b0), "r"(b1));
}

// SMEM layout (bytes). B tile: 128 rows x 272B pitch
#define XPITCH 272
#define OFF_A    0
#define OFF_B    512
#define SMEM_TOT (OFF_B + 128 * XPITCH)  // 35328

// ---------------------------------------------------------------------------
// Arg bundle for gemm
// ---------------------------------------------------------------------------
struct GA {
    const float* X;
    const __half* B;
    __half* Yh;
    float*  Yf;
    const float* aA; const float* aB;
    float* sA; float* sB;
    int N;
};

// ---------------------------------------------------------------------------
// Prep (merged): B[n][k] = fp16(Wa[k][n]) (n<64) else fp16(Wb[k][n-64]).
// ---------------------------------------------------------------------------
__global__ void pre_w_k(const float* __restrict__ Wa1, const float* __restrict__ Wb1,
                        __half* __restrict__ B1,
                        const float* __restrict__ Wa2, const float* __restrict__ Wb2,
                        __half* __restrict__ B2) {
    int which = blockIdx.x >> 6;
    int idx = (blockIdx.x & 63) * 256 + threadIdx.x;
    const float* Wa = which ? Wa2 : Wa1;
    const float* Wb = which ? Wb2 : Wb1;
    __half* B = which ? B2 : B1;
    int n = idx >> 7, k = idx & 127;
    float w = (n < 64) ? Wa[k * 64 + n] : Wb[k * 64 + (n - 64)];
    B[n * BPITCH + k] = __float2half_rn(w);
}

// ---------------------------------------------------------------------------
// zero kernel
// ---------------------------------------------------------------------------
__global__ void zero_k(float* __restrict__ p, size_t nf) {
    size_t i = ((size_t)blockIdx.x * blockDim.x + threadIdx.x) * 4;
    if (i + 4 <= nf) {
        *(float4*)(p + i) = make_float4(0.f, 0.f, 0.f, 0.f);
    } else {
        for (; i < nf; i++) p[i] = 0.f;
    }
}

// ---------------------------------------------------------------------------
// Merged fp16 HMMA GEMM (R12 best — unchanged)
// ---------------------------------------------------------------------------
__global__ __launch_bounds__(256, 2)
void gemm_tc(GA g1, GA g2, int nb1)
{
    extern __shared__ char sm[];
    const uint32_t sb = smem_u32(sm);
    const int tid = threadIdx.x, wid = tid >> 5, lane = tid & 31;

    const bool first = blockIdx.x < (unsigned)nb1;
    const GA g = first ? g1 : g2;
    const int row0 = (first ? blockIdx.x : blockIdx.x - nb1) * 128;

    {
        const float4* bsrc = (const float4*)g.B;
        float4* bdst = (float4*)(sm + OFF_B);
        const int n4 = 128 * BPITCH * 2 / 16;   // 2176
        for (int i = tid; i < n4; i += 256) bdst[i] = bsrc[i];
    }
    if (tid < 64)       ((float*)(sm + OFF_A))[tid] = __ldg(&g.aA[tid]);
    else if (tid < 128) ((float*)(sm + OFF_A))[tid] = __ldg(&g.aB[tid - 64]);

    const int wm = wid & 3, wn = wid >> 2;
    const int c0 = (lane & 3) * 2;

    const int rb = row0 + wm * 32 + (lane >> 2);
    int rows[4] = {rb, rb + 8, rb + 16, rb + 24};
    bool ok[4];
    const float* xp[4];
#pragma unroll
    for (int m = 0; m < 4; m++) {
        ok[m] = rows[m] < g.N;
        xp[m] = g.X + (size_t)(ok[m] ? rows[m] : 0) * DI + c0;
    }

    __syncthreads();

    float c[16][4];
#pragma unroll
    for (int j = 0; j < 16; j++)
#pragma unroll
        for (int q = 0; q < 4; q++) c[j][q] = 0.f;

    const int brow = (lane & 7) + ((lane >> 4) & 1) * 8;
    const int bkk  = ((lane >> 3) & 1) * 8;
    const uint32_t bbase = sb + OFF_B + (wn * 64 + brow) * XPITCH + bkk * 2;

#pragma unroll
    for (int s = 0; s < 8; s++) {
        const int ks = s * 16;
        float2 v[8];
#pragma unroll
        for (int m = 0; m < 4; m++) {
            v[m]     = ok[m] ? *(const float2*)(xp[m] + ks)     : make_float2(0.f, 0.f);
            v[m + 4] = ok[m] ? *(const float2*)(xp[m] + ks + 8) : make_float2(0.f, 0.f);
        }
        uint32_t ah0[4], ah1[4];
        {
            __half2 h;
            h = __floats2half2_rn(v[0].x, v[0].y); ah0[0] = *(uint32_t*)&h;
            h = __floats2half2_rn(v[1].x, v[1].y); ah0[1] = *(uint32_t*)&h;
            h = __floats2half2_rn(v[4].x, v[4].y); ah0[2] = *(uint32_t*)&h;
            h = __floats2half2_rn(v[5].x, v[5].y); ah0[3] = *(uint32_t*)&h;
            h = __floats2half2_rn(v[2].x, v[2].y); ah1[0] = *(uint32_t*)&h;
            h = __floats2half2_rn(v[3].x, v[3].y); ah1[1] = *(uint32_t*)&h;
            h = __floats2half2_rn(v[6].x, v[6].y); ah1[2] = *(uint32_t*)&h;
            h = __floats2half2_rn(v[7].x, v[7].y); ah1[3] = *(uint32_t*)&h;
        }

#pragma unroll
        for (int p = 0; p < 4; p++) {
            uint32_t bh[4];
            uint32_t boff = (uint32_t)(p * 16) * XPITCH + ks * 2;
            ldm_x4(bh, bbase + boff);
            mma_f16(c[2 * p],         ah0, bh[0], bh[1]);
            mma_f16(c[2 * p + 1],     ah0, bh[2], bh[3]);
            mma_f16(c[8 + 2 * p],     ah1, bh[0], bh[1]);
            mma_f16(c[8 + 2 * p + 1], ah1, bh[2], bh[3]);
        }
    }

    const float* av = (const float*)(sm + OFF_A) + wn * 64;
    float* sOut = wn ? g.sB : g.sA;

    float sc[4] = {0.f, 0.f, 0.f, 0.f};
#pragma unroll
    for (int n = 0; n < 8; n++) {
        int col = n * 8 + c0;
        float a0 = av[col], a1 = av[col + 1];
        sc[0] += c[n][0] * a0 + c[n][1] * a1;
        sc[1] += c[n][2] * a0 + c[n][3] * a1;
        sc[2] += c[8 + n][0] * a0 + c[8 + n][1] * a1;
        sc[3] += c[8 + n][2] * a0 + c[8 + n][3] * a1;
        if (wn == 0) {
            if (ok[0]) *(__half2*)&g.Yh[(size_t)rows[0] * DO + col] =
                __floats2half2_rn(c[n][0], c[n][1]);
            if (ok[1]) *(__half2*)&g.Yh[(size_t)rows[1] * DO + col] =
                __floats2half2_rn(c[n][2], c[n][3]);
            if (ok[2]) *(__half2*)&g.Yh[(size_t)rows[2] * DO + col] =
                __floats2half2_rn(c[8 + n][0], c[8 + n][1]);
            if (ok[3]) *(__half2*)&g.Yh[(size_t)rows[3] * DO + col] =
                __floats2half2_rn(c[8 + n][2], c[8 + n][3]);
        } else {
            if (ok[0]) *(float2*)&g.Yf[(size_t)rows[0] * DO + col] = make_float2(c[n][0], c[n][1]);
            if (ok[1]) *(float2*)&g.Yf[(size_t)rows[1] * DO + col] = make_float2(c[n][2], c[n][3]);
            if (ok[2]) *(float2*)&g.Yf[(size_t)rows[2] * DO + col] = make_float2(c[8 + n][0], c[8 + n][1]);
            if (ok[3]) *(float2*)&g.Yf[(size_t)rows[3] * DO + col] = make_float2(c[8 + n][2], c[8 + n][3]);
        }
    }
#pragma unroll
    for (int o = 1; o <= 2; o <<= 1) {
#pragma unroll
        for (int m = 0; m < 4; m++) sc[m] += __shfl_xor_sync(0xffffffffu, sc[m], o);
    }
    if ((lane & 3) == 0) {
#pragma unroll
        for (int m = 0; m < 4; m++)
            if (ok[m]) sOut[rows[m]] = sc[m];
    }
}

// ---------------------------------------------------------------------------
// CSR build: histogram
// ---------------------------------------------------------------------------
__global__ __launch_bounds__(256) void hist_k(
    const int* __restrict__ tgt_ui, int Eui,
    const int* __restrict__ tgt_iu, int Eiu,
    int* __restrict__ cnt_ui, int* __restrict__ cnt_iu)
{
    int i = blockIdx.x * 256 + threadIdx.x;
    if (i < Eui) atomicAdd(&cnt_ui[__ldg(&tgt_ui[i])], 1);
    else if (i < Eui + Eiu) atomicAdd(&cnt_iu[__ldg(&tgt_iu[i - Eui])], 1);
}

// ---------------------------------------------------------------------------
// Per-1024-target block sums
// ---------------------------------------------------------------------------
__global__ __launch_bounds__(256) void bsum_k(
    const int* __restrict__ cnt_ui, int Ni, int* __restrict__ bsum_ui, int nb_ui,
    const int* __restrict__ cnt_iu, int Nu, int* __restrict__ bsum_iu)
{
    __shared__ int s[256];
    int b = blockIdx.x;
    const int* cnt; int N; int* bsum; int lb;
    if (b < nb_ui) { cnt = cnt_ui; N = Ni; bsum = bsum_ui; lb = b; }
    else           { cnt = cnt_iu; N = Nu; bsum = bsum_iu; lb = b - nb_ui; }
    int base = lb * 1024;
    int v = 0;
    for (int j = threadIdx.x; j < 1024; j += 256) {
        int t = base + j;
        if (t < N) v += cnt[t];
    }
    s[threadIdx.x] = v;
    __syncthreads();
    for (int d = 128; d; d >>= 1) {
        if (threadIdx.x < d) s[threadIdx.x] += s[threadIdx.x + d];
        __syncthreads();
    }
    if (threadIdx.x == 0) bsum[lb] = s[0];
}

// ---------------------------------------------------------------------------
// Scan of block sums (tiny; single block)
// ---------------------------------------------------------------------------
__global__ void tops_k(const int* __restrict__ bsum_ui, int nb_ui, int* __restrict__ bofs_ui,
                       const int* __restrict__ bsum_iu, int nb_iu, int* __restrict__ bofs_iu)
{
    if (threadIdx.x == 0) {
        int acc = 0;
        for (int i = 0; i < nb_ui; i++) { bofs_ui[i] = acc; acc += bsum_ui[i]; }
    }
    if (threadIdx.x == 1) {
        int acc = 0;
        for (int i = 0; i < nb_iu; i++) { bofs_iu[i] = acc; acc += bsum_iu[i]; }
    }
}

// ---------------------------------------------------------------------------
// Per-block exclusive scan + global offset -> ofs, cursor
// ---------------------------------------------------------------------------
__global__ __launch_bounds__(1024) void bofs_k(
    const int* __restrict__ cnt_ui, int Ni, const int* __restrict__ bofs_ui,
    int* __restrict__ ofs_ui, int* __restrict__ cur_ui, int nb_ui,
    const int* __restrict__ cnt_iu, int Nu, const int* __restrict__ bofs_iu,
    int* __restrict__ ofs_iu, int* __restrict__ cur_iu)
{
    __shared__ int s[1024];
    int b = blockIdx.x;
    const int* cnt; int N; const int* bofs; int* ofs; int* cur; int lb;
    if (b < nb_ui) { cnt = cnt_ui; N = Ni; bofs = bofs_ui; ofs = ofs_ui; cur = cur_ui; lb = b; }
    else           { cnt = cnt_iu; N = Nu; bofs = bofs_iu; ofs = ofs_iu; cur = cur_iu; lb = b - nb_ui; }
    int t = lb * 1024 + threadIdx.x;
    int v = (t < N) ? cnt[t] : 0;
    s[threadIdx.x] = v;
    __syncthreads();
    for (int d = 1; d < 1024; d <<= 1) {
        int x = (threadIdx.x >= d) ? s[threadIdx.x - d] : 0;
        __syncthreads();
        s[threadIdx.x] += x;
        __syncthreads();
    }
    int excl = s[threadIdx.x] - v + bofs[lb];
    if (t < N) { ofs[t] = excl; cur[t] = excl; }
}

// ---------------------------------------------------------------------------
// Scatter: per edge compute att, place (src, att) at sorted position.
// ---------------------------------------------------------------------------
__global__ __launch_bounds__(256) void scatter_k(
    const int* __restrict__ src_ui, const int* __restrict__ tgt_ui, int Eui,
    const int* __restrict__ src_iu, const int* __restrict__ tgt_iu, int Eiu,
    const float* __restrict__ ss_ui, const float* __restrict__ ts_ui,
    const float* __restrict__ ss_iu, const float* __restrict__ ts_iu,
    int* __restrict__ cur_ui, int* __restrict__ cur_iu,
    uint2* __restrict__ sorted_ui, uint2* __restrict__ sorted_iu)
{
    int i = blockIdx.x * 256 + threadIdx.x;
    if (i < Eui) {
        int s = __ldg(&src_ui[i]);
        int t = __ldg(&tgt_ui[i]);
        float sc = __ldg(&ss_ui[s]) + __ldg(&ts_ui[t]);
        float att = expf(sc >= 0.f ? sc : 0.2f * sc);
        int pos = atomicAdd(&cur_ui[t], 1);
        sorted_ui[pos] = make_uint2((unsigned)s, __float_as_uint(att));
    } else if (i < Eui + Eiu) {
        int j = i - Eui;
        int s = __ldg(&src_iu[j]);
        int t = __ldg(&tgt_iu[j]);
        float sc = __ldg(&ss_iu[s]) + __ldg(&ts_iu[t]);
        float att = expf(sc >= 0.f ? sc : 0.2f * sc);
        int pos = atomicAdd(&cur_iu[t], 1);
        sorted_iu[pos] = make_uint2((unsigned)s, __float_as_uint(att));
    }
}

// ---------------------------------------------------------------------------
// Aggregate + finalize: 16 lanes per target. Walk CSR list, fp16 feature
// gather, fp32 register accumulation, write out = tx + acc/(den+eps).
// Targets [0,Nu) = users (iu edges); [Nu,Nu+Ni) = items (ui edges).
// ---------------------------------------------------------------------------
__global__ __launch_bounds__(256) void agg_k(
    const int* __restrict__ ofs_iu, const int* __restrict__ cnt_iu,
    const uint2* __restrict__ sorted_iu, const uint2* __restrict__ feat_iu,
    const float4* __restrict__ tx_u,
    const int* __restrict__ ofs_ui, const int* __restrict__ cnt_ui,
    const uint2* __restrict__ sorted_ui, const uint2* __restrict__ feat_ui,
    const float4* __restrict__ tx_i,
    float4* __restrict__ out, int Nu, int Ntot)
{
    int g = blockIdx.x * 16 + (threadIdx.x >> 4);
    int lane = threadIdx.x & 15;
    if (g >= Ntot) return;
    const int* ofs; const int* cnt; const uint2* sorted; const uint2* feat;
    const float4* tx;
    int t;
    if (g < Nu) { t = g;      ofs = ofs_iu; cnt = cnt_iu; sorted = sorted_iu; feat = feat_iu; tx = tx_u; }
    else        { t = g - Nu; ofs = ofs_ui; cnt = cnt_ui; sorted = sorted_ui; feat = feat_ui; tx = tx_i; }

    int beg = __ldg(&ofs[t]);
    int num = __ldg(&cnt[t]);
    float ax = 0.f, ay = 0.f, az = 0.f, aw = 0.f, den = 0.f;

    int e = beg, end = beg + num;
    for (; e + 1 < end; e += 2) {
        uint2 sa0 = __ldg(&sorted[e]);
        uint2 sa1 = __ldg(&sorted[e + 1]);
        uint2 u0 = __ldg(&feat[(size_t)sa0.x * 16 + lane]);
        uint2 u1 = __ldg(&feat[(size_t)sa1.x * 16 + lane]);
        float at0 = __uint_as_float(sa0.y);
        float at1 = __uint_as_float(sa1.y);
        float2 f00 = __half22float2(*(__half2*)&u0.x);
        float2 f01 = __half22float2(*(__half2*)&u0.y);
        float2 f10 = __half22float2(*(__half2*)&u1.x);
        float2 f11 = __half22float2(*(__half2*)&u1.y);
        ax += at0 * f00.x + at1 * f10.x;
        ay += at0 * f00.y + at1 * f10.y;
        az += at0 * f01.x + at1 * f11.x;
        aw += at0 * f01.y + at1 * f11.y;
        den += at0 + at1;
    }
    if (e < end) {
        uint2 sa = __ldg(&sorted[e]);
        uint2 u = __ldg(&feat[(size_t)sa.x * 16 + lane]);
        float at = __uint_as_float(sa.y);
        float2 f0 = __half22float2(*(__half2*)&u.x);
        float2 f1 = __half22float2(*(__half2*)&u.y);
        ax += at * f0.x; ay += at * f0.y;
        az += at * f1.x; aw += at * f1.y;
        den += at;
    }

    float inv = 1.f / (den + 1e-6f);
    float4 t4 = __ldg(&tx[(size_t)t * 16 + lane]);
    out[(size_t)g * 16 + lane] = make_float4(
        t4.x + ax * inv, t4.y + ay * inv, t4.z + az * inv, t4.w + aw * inv);
}

// ---------------------------------------------------------------------------
extern "C" void kernel_launch(void* const* d_in, const int* in_sizes, int n_in,
                              void* d_out, int out_size)
{
    const float* x_user   = (const float*)d_in[0];
    const float* x_item   = (const float*)d_in[1];
    const float* W_ui_src = (const float*)d_in[2];
    const float* W_ui_tgt = (const float*)d_in[3];
    const float* W_iu_src = (const float*)d_in[4];
    const float* W_iu_tgt = (const float*)d_in[5];
    const float* a_ui     = (const float*)d_in[6];
    const float* a_iu     = (const float*)d_in[7];
    const int*   edge_ui  = (const int*)d_in[8];
    const int*   edge_iu  = (const int*)d_in[9];
    float* out = (float*)d_out;

    const int Nu  = in_sizes[0] / DI;
    const int Ni  = in_sizes[1] / DI;
    const int Eui = in_sizes[8] / 2;
    const int Eiu = in_sizes[9] / 2;

    float* base = nullptr;
    cudaGetSymbolAddress((void**)&base, g_scratch);
    __half *B1, *B2;
    cudaGetSymbolAddress((void**)&B1, g_B1);
    cudaGetSymbolAddress((void**)&B2, g_B2);

    float* s = base;
    __half* sxh_ui  = (__half*)s; s += (size_t)Nu * DO / 2;
    float*  tx_iu   = s;          s += (size_t)Nu * DO;
    __half* sxh_iu  = (__half*)s; s += (size_t)Ni * DO / 2;
    float*  tx_ui   = s;          s += (size_t)Ni * DO;
    float*  ss_ui   = s;          s += Nu;
    float*  ts_ui   = s;          s += Ni;
    float*  ss_iu   = s;          s += Ni;
    float*  ts_iu   = s;          s += Nu;
    int*    cnt_ui  = (int*)s;    s += Ni;
    int*    cnt_iu  = (int*)s;    s += Nu;
    int*    ofs_ui  = (int*)s;    s += Ni;
    int*    ofs_iu  = (int*)s;    s += Nu;
    int*    cur_ui  = (int*)s;    s += Ni;
    int*    cur_iu  = (int*)s;    s += Nu;
    int*    bsum_ui = (int*)s;    s += 128;
    int*    bsum_iu = (int*)s;    s += 128;
    int*    bofs_ui = (int*)s;    s += 128;
    int*    bofs_iu = (int*)s;    s += 128;
    uint2*  sorted_ui = (uint2*)s; s += 2 * (size_t)EMAX;
    uint2*  sorted_iu = (uint2*)s; s += 2 * (size_t)EMAX;

    const int nb_ui = (Ni + 1023) >> 10;
    const int nb_iu = (Nu + 1023) >> 10;

    cudaFuncSetAttribute(gemm_tc, cudaFuncAttributeMaxDynamicSharedMemorySize, SMEM_TOT);

    // Zero cnt arrays (contiguous: cnt_ui, cnt_iu)
    {
        size_t zf = (size_t)Ni + (size_t)Nu;
        int blocks = (int)((zf / 4 + 255) / 256) + 1;
        zero_k<<<blocks, 256>>>((float*)cnt_ui, zf);
    }

    // Prep fp16 B images
    pre_w_k<<<128, 256>>>(W_ui_src, W_iu_tgt, B1,
                          W_iu_src, W_ui_tgt, B2);

    // CSR build (independent of gemm)
    hist_k<<<(Eui + Eiu + 255) / 256, 256>>>(
        edge_ui + Eui, Eui, edge_iu + Eiu, Eiu, cnt_ui, cnt_iu);
    bsum_k<<<nb_ui + nb_iu, 256>>>(cnt_ui, Ni, bsum_ui, nb_ui, cnt_iu, Nu, bsum_iu);
    tops_k<<<1, 32>>>(bsum_ui, nb_ui, bofs_ui, bsum_iu, nb_iu, bofs_iu);
    bofs_k<<<nb_ui + nb_iu, 1024>>>(cnt_ui, Ni, bofs_ui, ofs_ui, cur_ui, nb_ui,
                                    cnt_iu, Nu, bofs_iu, ofs_iu, cur_iu);

    // Merged fp16 projections + fused node scores
    {
        GA g1 = {x_user, B1, sxh_ui, tx_iu, a_ui, a_iu + DO, ss_ui, ts_iu, Nu};
        GA g2 = {x_item, B2, sxh_iu, tx_ui, a_iu, a_ui + DO, ss_iu, ts_ui, Ni};
        int nb1 = (Nu + 127) / 128;
        int nb2 = (Ni + 127) / 128;
        gemm_tc<<<nb1 + nb2, 256, SMEM_TOT>>>(g1, g2, nb1);
    }

    // Scatter edges into CSR order with att
    scatter_k<<<(Eui + Eiu + 255) / 256, 256>>>(
        edge_ui, edge_ui + Eui, Eui,
        edge_iu, edge_iu + Eiu, Eiu,
        ss_ui, ts_ui, ss_iu, ts_iu,
        cur_ui, cur_iu, sorted_ui, sorted_iu);

    // Aggregate + finalize directly into out
    {
        int Ntot = Nu + Ni;
        agg_k<<<(Ntot + 15) / 16, 256>>>(
            ofs_iu, cnt_iu, sorted_iu, (const uint2*)sxh_iu, (const float4*)tx_iu,
            ofs_ui, cnt_ui, sorted_ui, (const uint2*)sxh_ui, (const float4*)tx_ui,
            (float4*)out, Nu, Ntot);
    }
}

// round 15
// speedup vs baseline: 1.3851x; 1.0837x over previous
#include <cuda_runtime.h>
#include <cuda_fp16.h>
#include <cstdint>
#include <cstddef>

#define DI 128
#define DO 64
#define NMAX 100000
#define EMAX 1048576

// B image layout: [128 n][136 k-pitch] fp16 (272B row pitch)
#define BPITCH 136

// ---------------------------------------------------------------------------
// Scratch
// ---------------------------------------------------------------------------
__device__ __align__(16) float g_scratch[6 * (size_t)NMAX * DO + 6 * (size_t)NMAX];
__device__ __align__(16) __half g_B1[128 * BPITCH], g_B2[128 * BPITCH];

__device__ __forceinline__ uint32_t smem_u32(const void* p) {
    uint32_t a;
    asm("{ .reg .u64 t; cvta.to.shared.u64 t, %1; cvt.u32.u64 %0, t; }"
        : "=r"(a) : "l"(p));
    return a;
}

__device__ __forceinline__ void ldm_x4(uint32_t* r, uint32_t addr) {
    asm volatile("ldmatrix.sync.aligned.m8n8.x4.shared.b16 {%0,%1,%2,%3}, [%4];"
                 : "=r"(r[0]), "=r"(r[1]), "=r"(r[2]), "=r"(r[3]) : "r"(addr));
}

__device__ __forceinline__ void mma_f16(float* c, const uint32_t* a,
                                        uint32_t b0, uint32_t b1) {
    asm volatile("mma.sync.aligned.m16n8k16.row.col.f32.f16.f16.f32 "
                 "{%0,%1,%2,%3}, {%4,%5,%6,%7}, {%8,%9}, {%0,%1,%2,%3};"
                 : "+f"(c[0]), "+f"(c[1]), "+f"(c[2]), "+f"(c[3])
                 : "r"(a[0]), "r"(a[1]), "r"(a[2]), "r"(a[3]),
                   "r"(b0), "r"(b1));
}

// SMEM layout (bytes). B tile: 128 rows x 272B pitch
#define XPITCH 272
#define OFF_A    0
#define OFF_B    512
#define SMEM_TOT (OFF_B + 128 * XPITCH)  // 35328

// ---------------------------------------------------------------------------
// Arg bundle for gemm
// ---------------------------------------------------------------------------
struct GA {
    const float* X;
    const __half* B;
    __half* Yh;
    float*  Yf;
    const float* aA; const float* aB;
    float* sA; float* sB;
    int N;
};

// ---------------------------------------------------------------------------
// Prep (merged): B[n][k] = fp16(Wa[k][n]) (n<64) else fp16(Wb[k][n-64]).
// ---------------------------------------------------------------------------
__global__ void pre_w_k(const float* __restrict__ Wa1, const float* __restrict__ Wb1,
                        __half* __restrict__ B1,
                        const float* __restrict__ Wa2, const float* __restrict__ Wb2,
                        __half* __restrict__ B2) {
    int which = blockIdx.x >> 6;
    int idx = (blockIdx.x & 63) * 256 + threadIdx.x;
    const float* Wa = which ? Wa2 : Wa1;
    const float* Wb = which ? Wb2 : Wb1;
    __half* B = which ? B2 : B1;
    int n = idx >> 7, k = idx & 127;
    float w = (n < 64) ? Wa[k * 64 + n] : Wb[k * 64 + (n - 64)];
    B[n * BPITCH + k] = __float2half_rn(w);
}

// ---------------------------------------------------------------------------
// zero kernel
// ---------------------------------------------------------------------------
__global__ void zero_k(float* __restrict__ p, size_t nf) {
    size_t i = ((size_t)blockIdx.x * blockDim.x + threadIdx.x) * 4;
    if (i + 4 <= nf) {
        *(float4*)(p + i) = make_float4(0.f, 0.f, 0.f, 0.f);
    } else {
        for (; i < nf; i++) p[i] = 0.f;
    }
}

// ---------------------------------------------------------------------------
// Merged fp16 HMMA GEMM, warp tiling 8M x 1N: each warp owns 16 rows x 128
// cols. Every X row loaded from gmem exactly once (4 float2 loads/kstep).
// CTA tile 128 x 128 (Ya cols 0..63 = ntiles 0..7, Yb = ntiles 8..15).
// Every warp writes both Yh (fp16) and Yf (fp32) slices + both scores.
// ---------------------------------------------------------------------------
__global__ __launch_bounds__(256, 2)
void gemm_tc(GA g1, GA g2, int nb1)
{
    extern __shared__ char sm[];
    const uint32_t sb = smem_u32(sm);
    const int tid = threadIdx.x, wid = tid >> 5, lane = tid & 31;

    const bool first = blockIdx.x < (unsigned)nb1;
    const GA g = first ? g1 : g2;
    const int row0 = (first ? blockIdx.x : blockIdx.x - nb1) * 128;

    {
        const float4* bsrc = (const float4*)g.B;
        float4* bdst = (float4*)(sm + OFF_B);
        const int n4 = 128 * BPITCH * 2 / 16;   // 2176
        for (int i = tid; i < n4; i += 256) bdst[i] = bsrc[i];
    }
    if (tid < 64)       ((float*)(sm + OFF_A))[tid] = __ldg(&g.aA[tid]);
    else if (tid < 128) ((float*)(sm + OFF_A))[tid] = __ldg(&g.aB[tid - 64]);

    const int c0 = (lane & 3) * 2;

    const int r0g = row0 + wid * 16 + (lane >> 2);
    const int r1g = r0g + 8;
    const bool ok0 = r0g < g.N, ok1 = r1g < g.N;
    const float* x0 = g.X + (size_t)(ok0 ? r0g : 0) * DI + c0;
    const float* x1 = g.X + (size_t)(ok1 ? r1g : 0) * DI + c0;

    __syncthreads();

    float c[16][4];
#pragma unroll
    for (int j = 0; j < 16; j++)
#pragma unroll
        for (int q = 0; q < 4; q++) c[j][q] = 0.f;

    const int brow = (lane & 7) + ((lane >> 4) & 1) * 8;
    const int bkk  = ((lane >> 3) & 1) * 8;
    const uint32_t bbase = sb + OFF_B + brow * XPITCH + bkk * 2;

#pragma unroll
    for (int s = 0; s < 8; s++) {
        const int ks = s * 16;
        float2 v00 = ok0 ? *(const float2*)(x0 + ks)     : make_float2(0.f, 0.f);
        float2 v10 = ok1 ? *(const float2*)(x1 + ks)     : make_float2(0.f, 0.f);
        float2 v01 = ok0 ? *(const float2*)(x0 + ks + 8) : make_float2(0.f, 0.f);
        float2 v11 = ok1 ? *(const float2*)(x1 + ks + 8) : make_float2(0.f, 0.f);
        uint32_t ah[4];
        {
            __half2 h;
            h = __floats2half2_rn(v00.x, v00.y); ah[0] = *(uint32_t*)&h;
            h = __floats2half2_rn(v10.x, v10.y); ah[1] = *(uint32_t*)&h;
            h = __floats2half2_rn(v01.x, v01.y); ah[2] = *(uint32_t*)&h;
            h = __floats2half2_rn(v11.x, v11.y); ah[3] = *(uint32_t*)&h;
        }

#pragma unroll
        for (int p = 0; p < 8; p++) {
            uint32_t bh[4];
            uint32_t boff = (uint32_t)(p * 16) * XPITCH + ks * 2;
            ldm_x4(bh, bbase + boff);
            mma_f16(c[2 * p],     ah, bh[0], bh[1]);
            mma_f16(c[2 * p + 1], ah, bh[2], bh[3]);
        }
    }

    // Epilogue: ntiles 0..7 -> Yh (fp16) + score A; 8..15 -> Yf + score B.
    const float* aS = (const float*)(sm + OFF_A);
    float sA0 = 0.f, sA1 = 0.f, sB0 = 0.f, sB1 = 0.f;
#pragma unroll
    for (int n = 0; n < 8; n++) {
        int col = n * 8 + c0;
        float a0 = aS[col], a1 = aS[col + 1];
        sA0 += c[n][0] * a0 + c[n][1] * a1;
        sA1 += c[n][2] * a0 + c[n][3] * a1;
        if (ok0) *(__half2*)&g.Yh[(size_t)r0g * DO + col] =
            __floats2half2_rn(c[n][0], c[n][1]);
        if (ok1) *(__half2*)&g.Yh[(size_t)r1g * DO + col] =
            __floats2half2_rn(c[n][2], c[n][3]);
        float b0 = aS[64 + col], b1 = aS[64 + col + 1];
        sB0 += c[8 + n][0] * b0 + c[8 + n][1] * b1;
        sB1 += c[8 + n][2] * b0 + c[8 + n][3] * b1;
        if (ok0) *(float2*)&g.Yf[(size_t)r0g * DO + col] = make_float2(c[8 + n][0], c[8 + n][1]);
        if (ok1) *(float2*)&g.Yf[(size_t)r1g * DO + col] = make_float2(c[8 + n][2], c[8 + n][3]);
    }
#pragma unroll
    for (int o = 1; o <= 2; o <<= 1) {
        sA0 += __shfl_xor_sync(0xffffffffu, sA0, o);
        sA1 += __shfl_xor_sync(0xffffffffu, sA1, o);
        sB0 += __shfl_xor_sync(0xffffffffu, sB0, o);
        sB1 += __shfl_xor_sync(0xffffffffu, sB1, o);
    }
    if ((lane & 3) == 0) {
        if (ok0) { g.sA[r0g] = sA0; g.sB[r0g] = sB0; }
        if (ok1) { g.sA[r1g] = sA1; g.sB[r1g] = sB1; }
    }
}

// ---------------------------------------------------------------------------
// CSR build: histogram
// ---------------------------------------------------------------------------
__global__ __launch_bounds__(256) void hist_k(
    const int* __restrict__ tgt_ui, int Eui,
    const int* __restrict__ tgt_iu, int Eiu,
    int* __restrict__ cnt_ui, int* __restrict__ cnt_iu)
{
    int i = blockIdx.x * 256 + threadIdx.x;
    if (i < Eui) atomicAdd(&cnt_ui[__ldg(&tgt_ui[i])], 1);
    else if (i < Eui + Eiu) atomicAdd(&cnt_iu[__ldg(&tgt_iu[i - Eui])], 1);
}

// ---------------------------------------------------------------------------
// Per-1024-target block sums
// ---------------------------------------------------------------------------
__global__ __launch_bounds__(256) void bsum_k(
    const int* __restrict__ cnt_ui, int Ni, int* __restrict__ bsum_ui, int nb_ui,
    const int* __restrict__ cnt_iu, int Nu, int* __restrict__ bsum_iu)
{
    __shared__ int s[256];
    int b = blockIdx.x;
    const int* cnt; int N; int* bsum; int lb;
    if (b < nb_ui) { cnt = cnt_ui; N = Ni; bsum = bsum_ui; lb = b; }
    else           { cnt = cnt_iu; N = Nu; bsum = bsum_iu; lb = b - nb_ui; }
    int base = lb * 1024;
    int v = 0;
    for (int j = threadIdx.x; j < 1024; j += 256) {
        int t = base + j;
        if (t < N) v += cnt[t];
    }
    s[threadIdx.x] = v;
    __syncthreads();
    for (int d = 128; d; d >>= 1) {
        if (threadIdx.x < d) s[threadIdx.x] += s[threadIdx.x + d];
        __syncthreads();
    }
    if (threadIdx.x == 0) bsum[lb] = s[0];
}

// ---------------------------------------------------------------------------
// Per-block exclusive scan (with inlined scan of block sums) -> ofs, cursor
// ---------------------------------------------------------------------------
__global__ __launch_bounds__(1024) void bofs_k(
    const int* __restrict__ cnt_ui, int Ni, const int* __restrict__ bsum_ui,
    int* __restrict__ ofs_ui, int* __restrict__ cur_ui, int nb_ui,
    const int* __restrict__ cnt_iu, int Nu, const int* __restrict__ bsum_iu,
    int* __restrict__ ofs_iu, int* __restrict__ cur_iu)
{
    __shared__ int s[1024];
    __shared__ int boff;
    int b = blockIdx.x;
    const int* cnt; int N; const int* bsum; int* ofs; int* cur; int lb;
    if (b < nb_ui) { cnt = cnt_ui; N = Ni; bsum = bsum_ui; ofs = ofs_ui; cur = cur_ui; lb = b; }
    else           { cnt = cnt_iu; N = Nu; bsum = bsum_iu; ofs = ofs_iu; cur = cur_iu; lb = b - nb_ui; }

    // Inline scan of prior block sums (<=196 ints)
    if (threadIdx.x == 0) boff = 0;
    __syncthreads();
    {
        int acc = 0;
        for (int j = threadIdx.x; j < lb; j += 1024) acc += bsum[j];
        if (acc) atomicAdd(&boff, acc);
    }

    int t = lb * 1024 + threadIdx.x;
    int v = (t < N) ? cnt[t] : 0;
    s[threadIdx.x] = v;
    __syncthreads();
    for (int d = 1; d < 1024; d <<= 1) {
        int x = (threadIdx.x >= d) ? s[threadIdx.x - d] : 0;
        __syncthreads();
        s[threadIdx.x] += x;
        __syncthreads();
    }
    int excl = s[threadIdx.x] - v + boff;
    if (t < N) { ofs[t] = excl; cur[t] = excl; }
}

// ---------------------------------------------------------------------------
// Scatter: per edge compute att, place (src, att) at sorted position.
// ---------------------------------------------------------------------------
__global__ __launch_bounds__(256) void scatter_k(
    const int* __restrict__ src_ui, const int* __restrict__ tgt_ui, int Eui,
    const int* __restrict__ src_iu, const int* __restrict__ tgt_iu, int Eiu,
    const float* __restrict__ ss_ui, const float* __restrict__ ts_ui,
    const float* __restrict__ ss_iu, const float* __restrict__ ts_iu,
    int* __restrict__ cur_ui, int* __restrict__ cur_iu,
    uint2* __restrict__ sorted_ui, uint2* __restrict__ sorted_iu)
{
    int i = blockIdx.x * 256 + threadIdx.x;
    if (i < Eui) {
        int s = __ldg(&src_ui[i]);
        int t = __ldg(&tgt_ui[i]);
        float sc = __ldg(&ss_ui[s]) + __ldg(&ts_ui[t]);
        float att = expf(sc >= 0.f ? sc : 0.2f * sc);
        int pos = atomicAdd(&cur_ui[t], 1);
        sorted_ui[pos] = make_uint2((unsigned)s, __float_as_uint(att));
    } else if (i < Eui + Eiu) {
        int j = i - Eui;
        int s = __ldg(&src_iu[j]);
        int t = __ldg(&tgt_iu[j]);
        float sc = __ldg(&ss_iu[s]) + __ldg(&ts_iu[t]);
        float att = expf(sc >= 0.f ? sc : 0.2f * sc);
        int pos = atomicAdd(&cur_iu[t], 1);
        sorted_iu[pos] = make_uint2((unsigned)s, __float_as_uint(att));
    }
}

// ---------------------------------------------------------------------------
// Aggregate + finalize: 16 lanes per target (unchanged from R14).
// ---------------------------------------------------------------------------
__global__ __launch_bounds__(256) void agg_k(
    const int* __restrict__ ofs_iu, const int* __restrict__ cnt_iu,
    const uint2* __restrict__ sorted_iu, const uint2* __restrict__ feat_iu,
    const float4* __restrict__ tx_u,
    const int* __restrict__ ofs_ui, const int* __restrict__ cnt_ui,
    const uint2* __restrict__ sorted_ui, const uint2* __restrict__ feat_ui,
    const float4* __restrict__ tx_i,
    float4* __restrict__ out, int Nu, int Ntot)
{
    int g = blockIdx.x * 16 + (threadIdx.x >> 4);
    int lane = threadIdx.x & 15;
    if (g >= Ntot) return;
    const int* ofs; const int* cnt; const uint2* sorted; const uint2* feat;
    const float4* tx;
    int t;
    if (g < Nu) { t = g;      ofs = ofs_iu; cnt = cnt_iu; sorted = sorted_iu; feat = feat_iu; tx = tx_u; }
    else        { t = g - Nu; ofs = ofs_ui; cnt = cnt_ui; sorted = sorted_ui; feat = feat_ui; tx = tx_i; }

    int beg = __ldg(&ofs[t]);
    int num = __ldg(&cnt[t]);
    float ax = 0.f, ay = 0.f, az = 0.f, aw = 0.f, den = 0.f;

    int e = beg, end = beg + num;
    for (; e + 1 < end; e += 2) {
        uint2 sa0 = __ldg(&sorted[e]);
        uint2 sa1 = __ldg(&sorted[e + 1]);
        uint2 u0 = __ldg(&feat[(size_t)sa0.x * 16 + lane]);
        uint2 u1 = __ldg(&feat[(size_t)sa1.x * 16 + lane]);
        float at0 = __uint_as_float(sa0.y);
        float at1 = __uint_as_float(sa1.y);
        float2 f00 = __half22float2(*(__half2*)&u0.x);
        float2 f01 = __half22float2(*(__half2*)&u0.y);
        float2 f10 = __half22float2(*(__half2*)&u1.x);
        float2 f11 = __half22float2(*(__half2*)&u1.y);
        ax += at0 * f00.x + at1 * f10.x;
        ay += at0 * f00.y + at1 * f10.y;
        az += at0 * f01.x + at1 * f11.x;
        aw += at0 * f01.y + at1 * f11.y;
        den += at0 + at1;
    }
    if (e < end) {
        uint2 sa = __ldg(&sorted[e]);
        uint2 u = __ldg(&feat[(size_t)sa.x * 16 + lane]);
        float at = __uint_as_float(sa.y);
        float2 f0 = __half22float2(*(__half2*)&u.x);
        float2 f1 = __half22float2(*(__half2*)&u.y);
        ax += at * f0.x; ay += at * f0.y;
        az += at * f1.x; aw += at * f1.y;
        den += at;
    }

    float inv = 1.f / (den + 1e-6f);
    float4 t4 = __ldg(&tx[(size_t)t * 16 + lane]);
    out[(size_t)g * 16 + lane] = make_float4(
        t4.x + ax * inv, t4.y + ay * inv, t4.z + az * inv, t4.w + aw * inv);
}

// ---------------------------------------------------------------------------
extern "C" void kernel_launch(void* const* d_in, const int* in_sizes, int n_in,
                              void* d_out, int out_size)
{
    const float* x_user   = (const float*)d_in[0];
    const float* x_item   = (const float*)d_in[1];
    const float* W_ui_src = (const float*)d_in[2];
    const float* W_ui_tgt = (const float*)d_in[3];
    const float* W_iu_src = (const float*)d_in[4];
    const float* W_iu_tgt = (const float*)d_in[5];
    const float* a_ui     = (const float*)d_in[6];
    const float* a_iu     = (const float*)d_in[7];
    const int*   edge_ui  = (const int*)d_in[8];
    const int*   edge_iu  = (const int*)d_in[9];
    float* out = (float*)d_out;

    const int Nu  = in_sizes[0] / DI;
    const int Ni  = in_sizes[1] / DI;
    const int Eui = in_sizes[8] / 2;
    const int Eiu = in_sizes[9] / 2;

    float* base = nullptr;
    cudaGetSymbolAddress((void**)&base, g_scratch);
    __half *B1, *B2;
    cudaGetSymbolAddress((void**)&B1, g_B1);
    cudaGetSymbolAddress((void**)&B2, g_B2);

    float* s = base;
    __half* sxh_ui  = (__half*)s; s += (size_t)Nu * DO / 2;
    float*  tx_iu   = s;          s += (size_t)Nu * DO;
    __half* sxh_iu  = (__half*)s; s += (size_t)Ni * DO / 2;
    float*  tx_ui   = s;          s += (size_t)Ni * DO;
    float*  ss_ui   = s;          s += Nu;
    float*  ts_ui   = s;          s += Ni;
    float*  ss_iu   = s;          s += Ni;
    float*  ts_iu   = s;          s += Nu;
    int*    cnt_ui  = (int*)s;    s += Ni;
    int*    cnt_iu  = (int*)s;    s += Nu;
    int*    ofs_ui  = (int*)s;    s += Ni;
    int*    ofs_iu  = (int*)s;    s += Nu;
    int*    cur_ui  = (int*)s;    s += Ni;
    int*    cur_iu  = (int*)s;    s += Nu;
    int*    bsum_ui = (int*)s;    s += 128;
    int*    bsum_iu = (int*)s;    s += 128;
    uint2*  sorted_ui = (uint2*)s; s += 2 * (size_t)EMAX;
    uint2*  sorted_iu = (uint2*)s; s += 2 * (size_t)EMAX;

    const int nb_ui = (Ni + 1023) >> 10;
    const int nb_iu = (Nu + 1023) >> 10;

    cudaFuncSetAttribute(gemm_tc, cudaFuncAttributeMaxDynamicSharedMemorySize, SMEM_TOT);

    // Zero cnt arrays (contiguous: cnt_ui, cnt_iu)
    {
        size_t zf = (size_t)Ni + (size_t)Nu;
        int blocks = (int)((zf / 4 + 255) / 256) + 1;
        zero_k<<<blocks, 256>>>((float*)cnt_ui, zf);
    }

    // Prep fp16 B images
    pre_w_k<<<128, 256>>>(W_ui_src, W_iu_tgt, B1,
                          W_iu_src, W_ui_tgt, B2);

    // CSR build (independent of gemm)
    hist_k<<<(Eui + Eiu + 255) / 256, 256>>>(
        edge_ui + Eui, Eui, edge_iu + Eiu, Eiu, cnt_ui, cnt_iu);
    bsum_k<<<nb_ui + nb_iu, 256>>>(cnt_ui, Ni, bsum_ui, nb_ui, cnt_iu, Nu, bsum_iu);
    bofs_k<<<nb_ui + nb_iu, 1024>>>(cnt_ui, Ni, bsum_ui, ofs_ui, cur_ui, nb_ui,
                                    cnt_iu, Nu, bsum_iu, ofs_iu, cur_iu);

    // Merged fp16 projections + fused node scores
    {
        GA g1 = {x_user, B1, sxh_ui, tx_iu, a_ui, a_iu + DO, ss_ui, ts_iu, Nu};
        GA g2 = {x_item, B2, sxh_iu, tx_ui, a_iu, a_ui + DO, ss_iu, ts_ui, Ni};
        int nb1 = (Nu + 127) / 128;
        int nb2 = (Ni + 127) / 128;
        gemm_tc<<<nb1 + nb2, 256, SMEM_TOT>>>(g1, g2, nb1);
    }

    // Scatter edges into CSR order with att
    scatter_k<<<(Eui + Eiu + 255) / 256, 256>>>(
        edge_ui, edge_ui + Eui, Eui,
        edge_iu, edge_iu + Eiu, Eiu,
        ss_ui, ts_ui, ss_iu, ts_iu,
        cur_ui, cur_iu, sorted_ui, sorted_iu);

    // Aggregate + finalize directly into out
    {
        int Ntot = Nu + Ni;
        agg_k<<<(Ntot + 15) / 16, 256>>>(
            ofs_iu, cnt_iu, sorted_iu, (const uint2*)sxh_iu, (const float4*)tx_iu,
            ofs_ui, cnt_ui, sorted_ui, (const uint2*)sxh_ui, (const float4*)tx_ui,
            (float4*)out, Nu, Ntot);
    }
}

// round 17
// speedup vs baseline: 1.4014x; 1.0118x over previous
#include <cuda_runtime.h>
#include <cuda_fp16.h>
#include <cstdint>
#include <cstddef>

#define DI 128
#define DO 64
#define NMAX 100000
#define EMAX 1048576

// B image layout: [128 n][136 k-pitch] fp16 (272B row pitch)
#define BPITCH 136

// ---------------------------------------------------------------------------
// Scratch (zero-initialized at module load; cnt region is self-cleaning:
// bofs_k re-zeroes it every invocation for the next graph replay)
// ---------------------------------------------------------------------------
__device__ __align__(16) float g_scratch[6 * (size_t)NMAX * DO + 6 * (size_t)NMAX];
__device__ __align__(16) __half g_B1[128 * BPITCH], g_B2[128 * BPITCH];

__device__ __forceinline__ uint32_t smem_u32(const void* p) {
    uint32_t a;
    asm("{ .reg .u64 t; cvta.to.shared.u64 t, %1; cvt.u32.u64 %0, t; }"
        : "=r"(a) : "l"(p));
    return a;
}

__device__ __forceinline__ void ldm_x4(uint32_t* r, uint32_t addr) {
    asm volatile("ldmatrix.sync.aligned.m8n8.x4.shared.b16 {%0,%1,%2,%3}, [%4];"
                 : "=r"(r[0]), "=r"(r[1]), "=r"(r[2]), "=r"(r[3]) : "r"(addr));
}

__device__ __forceinline__ void mma_f16(float* c, const uint32_t* a,
                                        uint32_t b0, uint32_t b1) {
    asm volatile("mma.sync.aligned.m16n8k16.row.col.f32.f16.f16.f32 "
                 "{%0,%1,%2,%3}, {%4,%5,%6,%7}, {%8,%9}, {%0,%1,%2,%3};"
                 : "+f"(c[0]), "+f"(c[1]), "+f"(c[2]), "+f"(c[3])
                 : "r"(a[0]), "r"(a[1]), "r"(a[2]), "r"(a[3]),
                   "r"(b0), "r"(b1));
}

// SMEM layout (bytes). B tile: 128 rows x 272B pitch
#define XPITCH 272
#define OFF_A    0
#define OFF_B    512
#define SMEM_TOT (OFF_B + 128 * XPITCH)  // 35328

// ---------------------------------------------------------------------------
// Arg bundle for gemm
// ---------------------------------------------------------------------------
struct GA {
    const float* X;
    const __half* B;
    __half* Yh;
    float*  Yf;
    const float* aA; const float* aB;
    float* sA; float* sB;
    int N;
};

// ---------------------------------------------------------------------------
// init_k: fused pre_w + hist (independent of each other; cnt arrives zeroed
// from static init / previous invocation's bofs_k).
// Blocks [0,128): pre_w; rest: hist.
// ---------------------------------------------------------------------------
__global__ __launch_bounds__(256) void init_k(
    const float* __restrict__ Wa1, const float* __restrict__ Wb1, __half* __restrict__ B1,
    const float* __restrict__ Wa2, const float* __restrict__ Wb2, __half* __restrict__ B2,
    const int* __restrict__ tgt_ui, int Eui,
    const int* __restrict__ tgt_iu, int Eiu,
    int* __restrict__ cnt_ui, int* __restrict__ cnt_iu)
{
    int b = blockIdx.x;
    if (b < 128) {
        int which = b >> 6;
        int idx = (b & 63) * 256 + threadIdx.x;
        const float* Wa = which ? Wa2 : Wa1;
        const float* Wb = which ? Wb2 : Wb1;
        __half* B = which ? B2 : B1;
        int n = idx >> 7, k = idx & 127;
        float w = (n < 64) ? Wa[k * 64 + n] : Wb[k * 64 + (n - 64)];
        B[n * BPITCH + k] = __float2half_rn(w);
        return;
    }
    b -= 128;
    int i = b * 256 + threadIdx.x;
    if (i < Eui) atomicAdd(&cnt_ui[__ldg(&tgt_ui[i])], 1);
    else if (i < Eui + Eiu) atomicAdd(&cnt_iu[__ldg(&tgt_iu[i - Eui])], 1);
}

// ---------------------------------------------------------------------------
// Merged fp16 HMMA GEMM, warp tiling 8M x 1N + fused bsum tail blocks.
// Blocks [0, nbg): gemm; [nbg, ...): per-1024-target block sums.
// ---------------------------------------------------------------------------
__global__ __launch_bounds__(256, 2)
void gemm_tc(GA g1, GA g2, int nb1, int nbg,
             const int* __restrict__ cnt_ui, int Ni_, int* __restrict__ bsum_ui, int nbs_ui,
             const int* __restrict__ cnt_iu, int Nu_, int* __restrict__ bsum_iu)
{
    // --- bsum tail blocks ---
    if (blockIdx.x >= (unsigned)nbg) {
        __shared__ int sred[256];
        int b = blockIdx.x - nbg;
        const int* cnt; int N; int* bsum; int lb;
        if (b < nbs_ui) { cnt = cnt_ui; N = Ni_; bsum = bsum_ui; lb = b; }
        else            { cnt = cnt_iu; N = Nu_; bsum = bsum_iu; lb = b - nbs_ui; }
        int base = lb * 1024;
        int v = 0;
        for (int j = threadIdx.x; j < 1024; j += 256) {
            int t = base + j;
            if (t < N) v += cnt[t];
        }
        sred[threadIdx.x] = v;
        __syncthreads();
        for (int d = 128; d; d >>= 1) {
            if (threadIdx.x < d) sred[threadIdx.x] += sred[threadIdx.x + d];
            __syncthreads();
        }
        if (threadIdx.x == 0) bsum[lb] = sred[0];
        return;
    }

    // --- gemm blocks ---
    extern __shared__ char sm[];
    const uint32_t sb = smem_u32(sm);
    const int tid = threadIdx.x, wid = tid >> 5, lane = tid & 31;

    const bool first = blockIdx.x < (unsigned)nb1;
    const GA g = first ? g1 : g2;
    const int row0 = (first ? blockIdx.x : blockIdx.x - nb1) * 128;

    {
        const float4* bsrc = (const float4*)g.B;
        float4* bdst = (float4*)(sm + OFF_B);
        const int n4 = 128 * BPITCH * 2 / 16;   // 2176
        for (int i = tid; i < n4; i += 256) bdst[i] = bsrc[i];
    }
    if (tid < 64)       ((float*)(sm + OFF_A))[tid] = __ldg(&g.aA[tid]);
    else if (tid < 128) ((float*)(sm + OFF_A))[tid] = __ldg(&g.aB[tid - 64]);

    const int c0 = (lane & 3) * 2;

    const int r0g = row0 + wid * 16 + (lane >> 2);
    const int r1g = r0g + 8;
    const bool ok0 = r0g < g.N, ok1 = r1g < g.N;
    const float* x0 = g.X + (size_t)(ok0 ? r0g : 0) * DI + c0;
    const float* x1 = g.X + (size_t)(ok1 ? r1g : 0) * DI + c0;

    __syncthreads();

    float c[16][4];
#pragma unroll
    for (int j = 0; j < 16; j++)
#pragma unroll
        for (int q = 0; q < 4; q++) c[j][q] = 0.f;

    const int brow = (lane & 7) + ((lane >> 4) & 1) * 8;
    const int bkk  = ((lane >> 3) & 1) * 8;
    const uint32_t bbase = sb + OFF_B + brow * XPITCH + bkk * 2;

#pragma unroll
    for (int s = 0; s < 8; s++) {
        const int ks = s * 16;
        float2 v00 = ok0 ? *(const float2*)(x0 + ks)     : make_float2(0.f, 0.f);
        float2 v10 = ok1 ? *(const float2*)(x1 + ks)     : make_float2(0.f, 0.f);
        float2 v01 = ok0 ? *(const float2*)(x0 + ks + 8) : make_float2(0.f, 0.f);
        float2 v11 = ok1 ? *(const float2*)(x1 + ks + 8) : make_float2(0.f, 0.f);
        uint32_t ah[4];
        {
            __half2 h;
            h = __floats2half2_rn(v00.x, v00.y); ah[0] = *(uint32_t*)&h;
            h = __floats2half2_rn(v10.x, v10.y); ah[1] = *(uint32_t*)&h;
            h = __floats2half2_rn(v01.x, v01.y); ah[2] = *(uint32_t*)&h;
            h = __floats2half2_rn(v11.x, v11.y); ah[3] = *(uint32_t*)&h;
        }

#pragma unroll
        for (int p = 0; p < 8; p++) {
            uint32_t bh[4];
            uint32_t boff = (uint32_t)(p * 16) * XPITCH + ks * 2;
            ldm_x4(bh, bbase + boff);
            mma_f16(c[2 * p],     ah, bh[0], bh[1]);
            mma_f16(c[2 * p + 1], ah, bh[2], bh[3]);
        }
    }

    const float* aS = (const float*)(sm + OFF_A);
    float sA0 = 0.f, sA1 = 0.f, sB0 = 0.f, sB1 = 0.f;
#pragma unroll
    for (int n = 0; n < 8; n++) {
        int col = n * 8 + c0;
        float a0 = aS[col], a1 = aS[col + 1];
        sA0 += c[n][0] * a0 + c[n][1] * a1;
        sA1 += c[n][2] * a0 + c[n][3] * a1;
        if (ok0) *(__half2*)&g.Yh[(size_t)r0g * DO + col] =
            __floats2half2_rn(c[n][0], c[n][1]);
        if (ok1) *(__half2*)&g.Yh[(size_t)r1g * DO + col] =
            __floats2half2_rn(c[n][2], c[n][3]);
        float b0 = aS[64 + col], b1 = aS[64 + col + 1];
        sB0 += c[8 + n][0] * b0 + c[8 + n][1] * b1;
        sB1 += c[8 + n][2] * b0 + c[8 + n][3] * b1;
        if (ok0) *(float2*)&g.Yf[(size_t)r0g * DO + col] = make_float2(c[8 + n][0], c[8 + n][1]);
        if (ok1) *(float2*)&g.Yf[(size_t)r1g * DO + col] = make_float2(c[8 + n][2], c[8 + n][3]);
    }
#pragma unroll
    for (int o = 1; o <= 2; o <<= 1) {
        sA0 += __shfl_xor_sync(0xffffffffu, sA0, o);
        sA1 += __shfl_xor_sync(0xffffffffu, sA1, o);
        sB0 += __shfl_xor_sync(0xffffffffu, sB0, o);
        sB1 += __shfl_xor_sync(0xffffffffu, sB1, o);
    }
    if ((lane & 3) == 0) {
        if (ok0) { g.sA[r0g] = sA0; g.sB[r0g] = sB0; }
        if (ok1) { g.sA[r1g] = sA1; g.sB[r1g] = sB1; }
    }
}

// ---------------------------------------------------------------------------
// Per-block exclusive scan (shfl-based) + inlined scan of block sums.
// Also SELF-ZEROES cnt[t] for the next invocation (cnt is dead after this).
// ---------------------------------------------------------------------------
__global__ __launch_bounds__(1024) void bofs_k(
    int* __restrict__ cnt_ui, int Ni, const int* __restrict__ bsum_ui,
    int* __restrict__ ofs_ui, int* __restrict__ cur_ui, int nb_ui,
    int* __restrict__ cnt_iu, int Nu, const int* __restrict__ bsum_iu,
    int* __restrict__ ofs_iu, int* __restrict__ cur_iu)
{
    __shared__ int ws[32];
    __shared__ int boff_s;
    int b = blockIdx.x;
    int* cnt; int N; const int* bsum; int* ofs; int* cur; int lb;
    if (b < nb_ui) { cnt = cnt_ui; N = Ni; bsum = bsum_ui; ofs = ofs_ui; cur = cur_ui; lb = b; }
    else           { cnt = cnt_iu; N = Nu; bsum = bsum_iu; ofs = ofs_iu; cur = cur_iu; lb = b - nb_ui; }

    const int lanew = threadIdx.x & 31, w = threadIdx.x >> 5;
    if (threadIdx.x == 0) boff_s = 0;
    __syncthreads();
    {
        int acc = 0;
        for (int j = threadIdx.x; j < lb; j += 1024) acc += bsum[j];
#pragma unroll
        for (int o = 16; o; o >>= 1) acc += __shfl_xor_sync(0xffffffffu, acc, o);
        if (lanew == 0 && acc) atomicAdd(&boff_s, acc);
    }

    int t = lb * 1024 + threadIdx.x;
    int v = (t < N) ? cnt[t] : 0;
    int x = v;
#pragma unroll
    for (int d = 1; d < 32; d <<= 1) {
        int y = __shfl_up_sync(0xffffffffu, x, d);
        if (lanew >= d) x += y;
    }
    if (lanew == 31) ws[w] = x;
    __syncthreads();
    if (w == 0) {
        int y = ws[lanew];
        int z = y;
#pragma unroll
        for (int d = 1; d < 32; d <<= 1) {
            int q = __shfl_up_sync(0xffffffffu, z, d);
            if (lanew >= d) z += q;
        }
        ws[lanew] = z - y;   // exclusive warp offsets
    }
    __syncthreads();
    int excl = x - v + ws[w] + boff_s;
    if (t < N) {
        ofs[t] = excl;
        cur[t] = excl;
        cnt[t] = 0;          // self-zero for next invocation's hist
    }
}

// ---------------------------------------------------------------------------
// Scatter: per edge compute att, place (src, att) at sorted position.
// After this kernel, cur[t] == ofs[t] + degree[t] (used as 'end' by agg).
// ---------------------------------------------------------------------------
__global__ __launch_bounds__(256) void scatter_k(
    const int* __restrict__ src_ui, const int* __restrict__ tgt_ui, int Eui,
    const int* __restrict__ src_iu, const int* __restrict__ tgt_iu, int Eiu,
    const float* __restrict__ ss_ui, const float* __restrict__ ts_ui,
    const float* __restrict__ ss_iu, const float* __restrict__ ts_iu,
    int* __restrict__ cur_ui, int* __restrict__ cur_iu,
    uint2* __restrict__ sorted_ui, uint2* __restrict__ sorted_iu)
{
    int i = blockIdx.x * 256 + threadIdx.x;
    if (i < Eui) {
        int s = __ldg(&src_ui[i]);
        int t = __ldg(&tgt_ui[i]);
        float sc = __ldg(&ss_ui[s]) + __ldg(&ts_ui[t]);
        float att = expf(sc >= 0.f ? sc : 0.2f * sc);
        int pos = atomicAdd(&cur_ui[t], 1);
        sorted_ui[pos] = make_uint2((unsigned)s, __float_as_uint(att));
    } else if (i < Eui + Eiu) {
        int j = i - Eui;
        int s = __ldg(&src_iu[j]);
        int t = __ldg(&tgt_iu[j]);
        float sc = __ldg(&ss_iu[s]) + __ldg(&ts_iu[t]);
        float att = expf(sc >= 0.f ? sc : 0.2f * sc);
        int pos = atomicAdd(&cur_iu[t], 1);
        sorted_iu[pos] = make_uint2((unsigned)s, __float_as_uint(att));
    }
}

// ---------------------------------------------------------------------------
// Aggregate + finalize: 16 lanes per target, 4-way unrolled edge walk.
// Range per target: [ofs[t], cur[t]) (cur holds post-scatter end).
// ---------------------------------------------------------------------------
__global__ __launch_bounds__(256) void agg_k(
    const int* __restrict__ ofs_iu, const int* __restrict__ cur_iu,
    const uint2* __restrict__ sorted_iu, const uint2* __restrict__ feat_iu,
    const float4* __restrict__ tx_u,
    const int* __restrict__ ofs_ui, const int* __restrict__ cur_ui,
    const uint2* __restrict__ sorted_ui, const uint2* __restrict__ feat_ui,
    const float4* __restrict__ tx_i,
    float4* __restrict__ out, int Nu, int Ntot)
{
    int g = blockIdx.x * 16 + (threadIdx.x >> 4);
    int lane = threadIdx.x & 15;
    if (g >= Ntot) return;
    const int* ofs; const int* cur; const uint2* sorted; const uint2* feat;
    const float4* tx;
    int t;
    if (g < Nu) { t = g;      ofs = ofs_iu; cur = cur_iu; sorted = sorted_iu; feat = feat_iu; tx = tx_u; }
    else        { t = g - Nu; ofs = ofs_ui; cur = cur_ui; sorted = sorted_ui; feat = feat_ui; tx = tx_i; }

    int beg = __ldg(&ofs[t]);
    int end = __ldg(&cur[t]);
    float ax = 0.f, ay = 0.f, az = 0.f, aw = 0.f, den = 0.f;

    int e = beg;
    for (; e + 3 < end; e += 4) {
        uint2 sa0 = __ldg(&sorted[e]);
        uint2 sa1 = __ldg(&sorted[e + 1]);
        uint2 sa2 = __ldg(&sorted[e + 2]);
        uint2 sa3 = __ldg(&sorted[e + 3]);
        uint2 u0 = __ldg(&feat[(size_t)sa0.x * 16 + lane]);
        uint2 u1 = __ldg(&feat[(size_t)sa1.x * 16 + lane]);
        uint2 u2 = __ldg(&feat[(size_t)sa2.x * 16 + lane]);
        uint2 u3 = __ldg(&feat[(size_t)sa3.x * 16 + lane]);
        float at0 = __uint_as_float(sa0.y);
        float at1 = __uint_as_float(sa1.y);
        float at2 = __uint_as_float(sa2.y);
        float at3 = __uint_as_float(sa3.y);
        float2 f00 = __half22float2(*(__half2*)&u0.x);
        float2 f01 = __half22float2(*(__half2*)&u0.y);
        float2 f10 = __half22float2(*(__half2*)&u1.x);
        float2 f11 = __half22float2(*(__half2*)&u1.y);
        float2 f20 = __half22float2(*(__half2*)&u2.x);
        float2 f21 = __half22float2(*(__half2*)&u2.y);
        float2 f30 = __half22float2(*(__half2*)&u3.x);
        float2 f31 = __half22float2(*(__half2*)&u3.y);
        ax += at0 * f00.x + at1 * f10.x + at2 * f20.x + at3 * f30.x;
        ay += at0 * f00.y + at1 * f10.y + at2 * f20.y + at3 * f30.y;
        az += at0 * f01.x + at1 * f11.x + at2 * f21.x + at3 * f31.x;
        aw += at0 * f01.y + at1 * f11.y + at2 * f21.y + at3 * f31.y;
        den += (at0 + at1) + (at2 + at3);
    }
    for (; e < end; e++) {
        uint2 sa = __ldg(&sorted[e]);
        uint2 u = __ldg(&feat[(size_t)sa.x * 16 + lane]);
        float at = __uint_as_float(sa.y);
        float2 f0 = __half22float2(*(__half2*)&u.x);
        float2 f1 = __half22float2(*(__half2*)&u.y);
        ax += at * f0.x; ay += at * f0.y;
        az += at * f1.x; aw += at * f1.y;
        den += at;
    }

    float inv = 1.f / (den + 1e-6f);
    float4 t4 = __ldg(&tx[(size_t)t * 16 + lane]);
    out[(size_t)g * 16 + lane] = make_float4(
        t4.x + ax * inv, t4.y + ay * inv, t4.z + az * inv, t4.w + aw * inv);
}

// ---------------------------------------------------------------------------
extern "C" void kernel_launch(void* const* d_in, const int* in_sizes, int n_in,
                              void* d_out, int out_size)
{
    const float* x_user   = (const float*)d_in[0];
    const float* x_item   = (const float*)d_in[1];
    const float* W_ui_src = (const float*)d_in[2];
    const float* W_ui_tgt = (const float*)d_in[3];
    const float* W_iu_src = (const float*)d_in[4];
    const float* W_iu_tgt = (const float*)d_in[5];
    const float* a_ui     = (const float*)d_in[6];
    const float* a_iu     = (const float*)d_in[7];
    const int*   edge_ui  = (const int*)d_in[8];
    const int*   edge_iu  = (const int*)d_in[9];
    float* out = (float*)d_out;

    const int Nu  = in_sizes[0] / DI;
    const int Ni  = in_sizes[1] / DI;
    const int Eui = in_sizes[8] / 2;
    const int Eiu = in_sizes[9] / 2;

    float* base = nullptr;
    cudaGetSymbolAddress((void**)&base, g_scratch);
    __half *B1, *B2;
    cudaGetSymbolAddress((void**)&B1, g_B1);
    cudaGetSymbolAddress((void**)&B2, g_B2);

    float* s = base;
    __half* sxh_ui  = (__half*)s; s += (size_t)Nu * DO / 2;
    float*  tx_iu   = s;          s += (size_t)Nu * DO;
    __half* sxh_iu  = (__half*)s; s += (size_t)Ni * DO / 2;
    float*  tx_ui   = s;          s += (size_t)Ni * DO;
    float*  ss_ui   = s;          s += Nu;
    float*  ts_ui   = s;          s += Ni;
    float*  ss_iu   = s;          s += Ni;
    float*  ts_iu   = s;          s += Nu;
    int*    cnt_ui  = (int*)s;    s += Ni;
    int*    cnt_iu  = (int*)s;    s += Nu;
    int*    ofs_ui  = (int*)s;    s += Ni;
    int*    ofs_iu  = (int*)s;    s += Nu;
    int*    cur_ui  = (int*)s;    s += Ni;
    int*    cur_iu  = (int*)s;    s += Nu;
    int*    bsum_ui = (int*)s;    s += 128;
    int*    bsum_iu = (int*)s;    s += 128;
    uint2*  sorted_ui = (uint2*)s; s += 2 * (size_t)EMAX;
    uint2*  sorted_iu = (uint2*)s; s += 2 * (size_t)EMAX;

    const int nb_ui = (Ni + 1023) >> 10;
    const int nb_iu = (Nu + 1023) >> 10;

    cudaFuncSetAttribute(gemm_tc, cudaFuncAttributeMaxDynamicSharedMemorySize, SMEM_TOT);

    // Fused init: prep B images + histogram (cnt arrives zeroed — static init
    // on first call, bofs_k self-zero on subsequent calls)
    {
        int nhb = (Eui + Eiu + 255) / 256;
        init_k<<<128 + nhb, 256>>>(
            W_ui_src, W_iu_tgt, B1, W_iu_src, W_ui_tgt, B2,
            edge_ui + Eui, Eui, edge_iu + Eiu, Eiu, cnt_ui, cnt_iu);
    }

    // Merged gemm (+ fused bsum tail blocks)
    {
        GA g1 = {x_user, B1, sxh_ui, tx_iu, a_ui, a_iu + DO, ss_ui, ts_iu, Nu};
        GA g2 = {x_item, B2, sxh_iu, tx_ui, a_iu, a_ui + DO, ss_iu, ts_ui, Ni};
        int nb1 = (Nu + 127) / 128;
        int nb2 = (Ni + 127) / 128;
        int nbg = nb1 + nb2;
        gemm_tc<<<nbg + nb_ui + nb_iu, 256, SMEM_TOT>>>(
            g1, g2, nb1, nbg,
            cnt_ui, Ni, bsum_ui, nb_ui, cnt_iu, Nu, bsum_iu);
    }

    // Exclusive scan -> ofs, cursor (+ self-zero cnt)
    bofs_k<<<nb_ui + nb_iu, 1024>>>(cnt_ui, Ni, bsum_ui, ofs_ui, cur_ui, nb_ui,
                                    cnt_iu, Nu, bsum_iu, ofs_iu, cur_iu);

    // Scatter edges into CSR order with att
    scatter_k<<<(Eui + Eiu + 255) / 256, 256>>>(
        edge_ui, edge_ui + Eui, Eui,
        edge_iu, edge_iu + Eiu, Eiu,
        ss_ui, ts_ui, ss_iu, ts_iu,
        cur_ui, cur_iu, sorted_ui, sorted_iu);

    // Aggregate + finalize directly into out
    {
        int Ntot = Nu + Ni;
        agg_k<<<(Ntot + 15) / 16, 256>>>(
            ofs_iu, cur_iu, sorted_iu, (const uint2*)sxh_iu, (const float4*)tx_iu,
            ofs_ui, cur_ui, sorted_ui, (const uint2*)sxh_ui, (const float4*)tx_ui,
            (float4*)out, Nu, Ntot);
    }
}